// round 1
// baseline (speedup 1.0000x reference)
#include <cuda_runtime.h>
#include <math.h>

#define D_MODEL 768
#define NUM_HEADS 12
#define D_HEAD 64
#define NQ 8
#define BATCH 16
#define P_TOK 197
#define M_ROWS (BATCH * P_TOK)       // 3152
#define PAIRS (BATCH * BATCH)        // 256
#define SHALF (BATCH * NUM_HEADS * NQ * P_TOK)   // 302592
#define LN_EPS 1e-5f

// ---------------- scratch (device globals; no allocation allowed) -------------
__device__ float g_qln[NQ * D_MODEL];                       // LN'd q projection
__device__ float g_kv[M_ROWS * D_MODEL];                    // kv proj (then LN in place)
__device__ float g_s[2 * SHALF];                            // scores, both halves
__device__ float g_m[2 * BATCH * NUM_HEADS * NQ];           // per-half row max
__device__ float g_z[2 * BATCH * NUM_HEADS * NQ];           // per-half exp-sum
__device__ float g_a[2 * BATCH * NUM_HEADS * NQ * D_HEAD];  // per-half weighted kv sum
__device__ float g_p[2 * BATCH * NUM_HEADS * NQ * D_MODEL]; // A projected through out_w

// ---------------- kernel 1: q = LN(q_x @ q_w^T + q_b) -------------------------
__global__ void qproj_kernel(const float* __restrict__ qx, const float* __restrict__ qw,
                             const float* __restrict__ qb, const float* __restrict__ lw,
                             const float* __restrict__ lb) {
    int row = blockIdx.x;
    int t = threadIdx.x;
    __shared__ float xs[D_MODEL];
    __shared__ float red[D_MODEL];
    xs[t] = qx[row * D_MODEL + t];
    __syncthreads();
    float acc = qb[t];
    const float* wr = qw + t * D_MODEL;
    #pragma unroll 8
    for (int k = 0; k < D_MODEL; ++k) acc += xs[k] * wr[k];

    // mean
    red[t] = acc;
    __syncthreads();
    if (t < 256) red[t] += red[t + 256] + red[t + 512];
    __syncthreads();
    for (int s = 128; s > 0; s >>= 1) { if (t < s) red[t] += red[t + s]; __syncthreads(); }
    float mean = red[0] * (1.0f / D_MODEL);
    __syncthreads();
    // var
    float dv = acc - mean;
    red[t] = dv * dv;
    __syncthreads();
    if (t < 256) red[t] += red[t + 256] + red[t + 512];
    __syncthreads();
    for (int s = 128; s > 0; s >>= 1) { if (t < s) red[t] += red[t + s]; __syncthreads(); }
    float var = red[0] * (1.0f / D_MODEL);
    g_qln[row * D_MODEL + t] = dv * rsqrtf(var + LN_EPS) * lw[t] + lb[t];
}

// ---------------- kernel 2: kv GEMM: C[3152,768] = X @ W^T + b ----------------
// 128x128 tile, BK=8, 256 threads, 8x8 per-thread microtile, float4 smem loads.
__global__ __launch_bounds__(256) void kv_gemm_kernel(const float* __restrict__ X,
                                                      const float* __restrict__ W,
                                                      const float* __restrict__ bias) {
    __shared__ float As[8][128];
    __shared__ float Bs[8][128];
    int tid = threadIdx.x;
    int bm = blockIdx.y * 128, bn = blockIdx.x * 128;
    int lr = tid >> 1;          // 0..127
    int lk = (tid & 1) * 4;     // 0 or 4
    int tx = tid & 15, ty = tid >> 4;

    float acc[8][8];
    #pragma unroll
    for (int i = 0; i < 8; ++i)
        #pragma unroll
        for (int j = 0; j < 8; ++j) acc[i][j] = 0.0f;

    for (int k0 = 0; k0 < D_MODEL; k0 += 8) {
        int grow = bm + lr;
        float4 xa;
        if (grow < M_ROWS) xa = *(const float4*)(X + grow * D_MODEL + k0 + lk);
        else xa = make_float4(0.f, 0.f, 0.f, 0.f);
        float4 wb = *(const float4*)(W + (bn + lr) * D_MODEL + k0 + lk);
        As[lk + 0][lr] = xa.x; As[lk + 1][lr] = xa.y; As[lk + 2][lr] = xa.z; As[lk + 3][lr] = xa.w;
        Bs[lk + 0][lr] = wb.x; Bs[lk + 1][lr] = wb.y; Bs[lk + 2][lr] = wb.z; Bs[lk + 3][lr] = wb.w;
        __syncthreads();
        #pragma unroll
        for (int kk = 0; kk < 8; ++kk) {
            float4 a0 = *(const float4*)&As[kk][ty * 4];
            float4 a1 = *(const float4*)&As[kk][ty * 4 + 64];
            float4 b0 = *(const float4*)&Bs[kk][tx * 4];
            float4 b1 = *(const float4*)&Bs[kk][tx * 4 + 64];
            float ar[8] = {a0.x, a0.y, a0.z, a0.w, a1.x, a1.y, a1.z, a1.w};
            float br[8] = {b0.x, b0.y, b0.z, b0.w, b1.x, b1.y, b1.z, b1.w};
            #pragma unroll
            for (int i = 0; i < 8; ++i)
                #pragma unroll
                for (int j = 0; j < 8; ++j) acc[i][j] += ar[i] * br[j];
        }
        __syncthreads();
    }
    #pragma unroll
    for (int i = 0; i < 8; ++i) {
        int r = bm + ((i < 4) ? (ty * 4 + i) : (64 + ty * 4 + i - 4));
        if (r < M_ROWS) {
            #pragma unroll
            for (int j = 0; j < 8; ++j) {
                int c = bn + ((j < 4) ? (tx * 4 + j) : (64 + tx * 4 + j - 4));
                g_kv[r * D_MODEL + c] = acc[i][j] + bias[c];
            }
        }
    }
}

// ---------------- kernel 3: in-place LN over g_kv rows ------------------------
__global__ void kvln_kernel(const float* __restrict__ lw, const float* __restrict__ lb) {
    int row = blockIdx.x;
    int t = threadIdx.x;
    float* x = g_kv + row * D_MODEL;
    float v0 = x[t], v1 = x[t + 256], v2 = x[t + 512];
    __shared__ float red[256];
    red[t] = v0 + v1 + v2;
    __syncthreads();
    for (int s = 128; s > 0; s >>= 1) { if (t < s) red[t] += red[t + s]; __syncthreads(); }
    float mean = red[0] * (1.0f / D_MODEL);
    __syncthreads();
    float d0 = v0 - mean, d1 = v1 - mean, d2 = v2 - mean;
    red[t] = d0 * d0 + d1 * d1 + d2 * d2;
    __syncthreads();
    for (int s = 128; s > 0; s >>= 1) { if (t < s) red[t] += red[t + s]; __syncthreads(); }
    float rstd = rsqrtf(red[0] * (1.0f / D_MODEL) + LN_EPS);
    x[t]       = d0 * rstd * lw[t]       + lb[t];
    x[t + 256] = d1 * rstd * lw[t + 256] + lb[t + 256];
    x[t + 512] = d2 * rstd * lw[t + 512] + lb[t + 512];
}

// ---------------- kernel 4: scores S[half][b,h,q,p] = 0.125 * q_h . (kv+pos) --
__global__ void scores_kernel(const float* __restrict__ pos) {
    int b = blockIdx.x, h = blockIdx.y;
    __shared__ float qh[NQ][D_HEAD];
    for (int i = threadIdx.x; i < NQ * D_HEAD; i += blockDim.x) {
        int qi = i >> 6, d = i & 63;
        qh[qi][d] = g_qln[qi * D_MODEL + h * D_HEAD + d];
    }
    __syncthreads();
    for (int half = 0; half < 2; ++half) {
        for (int p = threadIdx.x; p < P_TOK; p += blockDim.x) {
            const float* kr = g_kv + (b * P_TOK + p) * D_MODEL + h * D_HEAD;
            const float* pr = pos + (half * P_TOK + p) * D_MODEL + h * D_HEAD;
            float acc[NQ];
            #pragma unroll
            for (int qi = 0; qi < NQ; ++qi) acc[qi] = 0.0f;
            #pragma unroll 8
            for (int d = 0; d < D_HEAD; ++d) {
                float kvv = kr[d] + pr[d];
                #pragma unroll
                for (int qi = 0; qi < NQ; ++qi) acc[qi] += qh[qi][d] * kvv;
            }
            float* S = g_s + half * SHALF + ((b * NUM_HEADS + h) * NQ) * P_TOK + p;
            #pragma unroll
            for (int qi = 0; qi < NQ; ++qi) S[qi * P_TOK] = acc[qi] * 0.125f;
        }
    }
}

// ---------------- kernel 5: per-half softmax partials (m, Z, A) ---------------
__global__ void stats_kernel(const float* __restrict__ pos) {
    int b = blockIdx.x, h = blockIdx.y, half = blockIdx.z;
    int tid = threadIdx.x;
    int w = tid >> 5, lane = tid & 31;   // warp per q
    __shared__ float e[NQ][P_TOK + 3];
    __shared__ float smax[NQ], ssum[NQ];

    const float* Srow = g_s + half * SHALF + ((b * NUM_HEADS + h) * NQ + w) * P_TOK;
    float mx = -1e30f;
    for (int p = lane; p < P_TOK; p += 32) mx = fmaxf(mx, Srow[p]);
    #pragma unroll
    for (int off = 16; off > 0; off >>= 1) mx = fmaxf(mx, __shfl_xor_sync(0xffffffffu, mx, off));
    float sum = 0.0f;
    for (int p = lane; p < P_TOK; p += 32) {
        float t = expf(Srow[p] - mx);
        e[w][p] = t;
        sum += t;
    }
    #pragma unroll
    for (int off = 16; off > 0; off >>= 1) sum += __shfl_xor_sync(0xffffffffu, sum, off);
    if (lane == 0) { smax[w] = mx; ssum[w] = sum; }
    if (lane == 0) {
        int idx = ((half * BATCH + b) * NUM_HEADS + h) * NQ + w;
        g_m[idx] = mx;
        g_z[idx] = sum;
    }
    __syncthreads();

    // A[q][d] = sum_p e[q][p] * (kv + pos)
    for (int i = tid; i < NQ * D_HEAD; i += blockDim.x) {
        int q = i >> 6, d = i & 63;
        float acc = 0.0f;
        const float* kcol = g_kv + b * P_TOK * D_MODEL + h * D_HEAD + d;
        const float* pcol = pos + half * P_TOK * D_MODEL + h * D_HEAD + d;
        for (int p = 0; p < P_TOK; ++p)
            acc += e[q][p] * (kcol[p * D_MODEL] + pcol[p * D_MODEL]);
        g_a[(((half * BATCH + b) * NUM_HEADS + h) * NQ + q) * D_HEAD + d] = acc;
    }
}

// ---------------- kernel 6: project partials: Pm[.,o] = A[.,d] @ out_w[o,h*64+d]
__global__ void pproj_kernel(const float* __restrict__ outw) {
    int b = blockIdx.x, h = blockIdx.y, half = blockIdx.z;
    __shared__ float Ash[NQ][D_HEAD];
    for (int i = threadIdx.x; i < NQ * D_HEAD; i += blockDim.x) {
        int q = i >> 6, d = i & 63;
        Ash[q][d] = g_a[(((half * BATCH + b) * NUM_HEADS + h) * NQ + q) * D_HEAD + d];
    }
    __syncthreads();
    for (int o = threadIdx.x; o < D_MODEL; o += blockDim.x) {
        const float* wr = outw + o * D_MODEL + h * D_HEAD;
        float acc[NQ];
        #pragma unroll
        for (int q = 0; q < NQ; ++q) acc[q] = 0.0f;
        #pragma unroll 8
        for (int d = 0; d < D_HEAD; ++d) {
            float wv = wr[d];
            #pragma unroll
            for (int q = 0; q < NQ; ++q) acc[q] += Ash[q][d] * wv;
        }
        #pragma unroll
        for (int q = 0; q < NQ; ++q)
            g_p[(((half * BATCH + b) * NUM_HEADS + h) * NQ + q) * D_MODEL + o] = acc[q];
    }
}

// ---------------- kernel 7: per-pair softmax merge + combine ------------------
__global__ void combine_kernel(const float* __restrict__ outb, float* __restrict__ out) {
    int pair = blockIdx.x;
    int q = blockIdx.y;
    int i = pair >> 4, j = pair & 15;
    int tid = threadIdx.x;
    __shared__ float c1[NUM_HEADS], c2[NUM_HEADS];
    if (tid < NUM_HEADS) {
        int h = tid;
        int i1 = ((0 * BATCH + i) * NUM_HEADS + h) * NQ + q;
        int i2 = ((1 * BATCH + j) * NUM_HEADS + h) * NQ + q;
        float m1 = g_m[i1], m2 = g_m[i2];
        float z1 = g_z[i1], z2 = g_z[i2];
        float m = fmaxf(m1, m2);
        float e1 = expf(m1 - m), e2 = expf(m2 - m);
        float zinv = 1.0f / (e1 * z1 + e2 * z2);
        c1[h] = e1 * zinv;
        c2[h] = e2 * zinv;
    }
    __syncthreads();
    for (int o = tid; o < D_MODEL; o += blockDim.x) {
        float acc = outb[o];
        #pragma unroll
        for (int h = 0; h < NUM_HEADS; ++h) {
            const float* p1 = g_p + (((0 * BATCH + i) * NUM_HEADS + h) * NQ + q) * D_MODEL;
            const float* p2 = g_p + (((1 * BATCH + j) * NUM_HEADS + h) * NQ + q) * D_MODEL;
            acc += c1[h] * p1[o] - c2[h] * p2[o];
        }
        out[(pair * NQ + q) * D_MODEL + o] = acc;
    }
}

// ---------------- launch ------------------------------------------------------
extern "C" void kernel_launch(void* const* d_in, const int* in_sizes, int n_in,
                              void* d_out, int out_size) {
    const float* q_x   = (const float*)d_in[0];
    const float* kv_x  = (const float*)d_in[1];
    const float* pos   = (const float*)d_in[2];
    const float* q_w   = (const float*)d_in[3];
    const float* q_b   = (const float*)d_in[4];
    const float* kv_w  = (const float*)d_in[5];
    const float* kv_b  = (const float*)d_in[6];
    const float* out_w = (const float*)d_in[7];
    const float* out_b = (const float*)d_in[8];
    const float* lnq_w = (const float*)d_in[9];
    const float* lnq_b = (const float*)d_in[10];
    const float* lnkv_w = (const float*)d_in[11];
    const float* lnkv_b = (const float*)d_in[12];
    float* out = (float*)d_out;

    qproj_kernel<<<NQ, D_MODEL>>>(q_x, q_w, q_b, lnq_w, lnq_b);
    kv_gemm_kernel<<<dim3(D_MODEL / 128, (M_ROWS + 127) / 128), 256>>>(kv_x, kv_w, kv_b);
    kvln_kernel<<<M_ROWS, 256>>>(lnkv_w, lnkv_b);
    scores_kernel<<<dim3(BATCH, NUM_HEADS), 256>>>(pos);
    stats_kernel<<<dim3(BATCH, NUM_HEADS, 2), 256>>>(pos);
    pproj_kernel<<<dim3(BATCH, NUM_HEADS, 2), 256>>>(out_w);
    combine_kernel<<<dim3(PAIRS, NQ), 256>>>(out_b, out);
}

// round 2
// speedup vs baseline: 1.0501x; 1.0501x over previous
#include <cuda_runtime.h>
#include <math.h>

#define D_MODEL 768
#define NUM_HEADS 12
#define D_HEAD 64
#define NQ 8
#define BATCH 16
#define P_TOK 197
#define M_ROWS (BATCH * P_TOK)       // 3152
#define PAIRS (BATCH * BATCH)        // 256
#define LN_EPS 1e-5f
#define TILE_LD 67                   // padded row stride (odd -> conflict-free LDS)

// ---------------- scratch (device globals; no allocation allowed) -------------
__device__ float g_qln[NQ * D_MODEL];                       // LN'd q projection
__device__ float g_kv[M_ROWS * D_MODEL];                    // kv proj (then LN in place)
__device__ float g_m[2 * BATCH * NUM_HEADS * NQ];           // per-half row max
__device__ float g_z[2 * BATCH * NUM_HEADS * NQ];           // per-half exp-sum
__device__ float g_p[2 * BATCH * NUM_HEADS * NQ * D_MODEL]; // A projected through out_w

// ---------------- kernel 1: q = LN(q_x @ q_w^T + q_b) -------------------------
__global__ void qproj_kernel(const float* __restrict__ qx, const float* __restrict__ qw,
                             const float* __restrict__ qb, const float* __restrict__ lw,
                             const float* __restrict__ lb) {
    int row = blockIdx.x;
    int t = threadIdx.x;
    __shared__ float xs[D_MODEL];
    __shared__ float red[D_MODEL];
    xs[t] = qx[row * D_MODEL + t];
    __syncthreads();
    float acc = qb[t];
    const float* wr = qw + t * D_MODEL;
    #pragma unroll 8
    for (int k = 0; k < D_MODEL; ++k) acc += xs[k] * wr[k];

    red[t] = acc;
    __syncthreads();
    if (t < 256) red[t] += red[t + 256] + red[t + 512];
    __syncthreads();
    for (int s = 128; s > 0; s >>= 1) { if (t < s) red[t] += red[t + s]; __syncthreads(); }
    float mean = red[0] * (1.0f / D_MODEL);
    __syncthreads();
    float dv = acc - mean;
    red[t] = dv * dv;
    __syncthreads();
    if (t < 256) red[t] += red[t + 256] + red[t + 512];
    __syncthreads();
    for (int s = 128; s > 0; s >>= 1) { if (t < s) red[t] += red[t + s]; __syncthreads(); }
    float var = red[0] * (1.0f / D_MODEL);
    g_qln[row * D_MODEL + t] = dv * rsqrtf(var + LN_EPS) * lw[t] + lb[t];
}

// ---------------- kernel 2: kv GEMM: C[3152,768] = X @ W^T + b ----------------
__global__ __launch_bounds__(256) void kv_gemm_kernel(const float* __restrict__ X,
                                                      const float* __restrict__ W,
                                                      const float* __restrict__ bias) {
    __shared__ float As[8][128];
    __shared__ float Bs[8][128];
    int tid = threadIdx.x;
    int bm = blockIdx.y * 128, bn = blockIdx.x * 128;
    int lr = tid >> 1;
    int lk = (tid & 1) * 4;
    int tx = tid & 15, ty = tid >> 4;

    float acc[8][8];
    #pragma unroll
    for (int i = 0; i < 8; ++i)
        #pragma unroll
        for (int j = 0; j < 8; ++j) acc[i][j] = 0.0f;

    for (int k0 = 0; k0 < D_MODEL; k0 += 8) {
        int grow = bm + lr;
        float4 xa;
        if (grow < M_ROWS) xa = *(const float4*)(X + grow * D_MODEL + k0 + lk);
        else xa = make_float4(0.f, 0.f, 0.f, 0.f);
        float4 wb = *(const float4*)(W + (bn + lr) * D_MODEL + k0 + lk);
        As[lk + 0][lr] = xa.x; As[lk + 1][lr] = xa.y; As[lk + 2][lr] = xa.z; As[lk + 3][lr] = xa.w;
        Bs[lk + 0][lr] = wb.x; Bs[lk + 1][lr] = wb.y; Bs[lk + 2][lr] = wb.z; Bs[lk + 3][lr] = wb.w;
        __syncthreads();
        #pragma unroll
        for (int kk = 0; kk < 8; ++kk) {
            float4 a0 = *(const float4*)&As[kk][ty * 4];
            float4 a1 = *(const float4*)&As[kk][ty * 4 + 64];
            float4 b0 = *(const float4*)&Bs[kk][tx * 4];
            float4 b1 = *(const float4*)&Bs[kk][tx * 4 + 64];
            float ar[8] = {a0.x, a0.y, a0.z, a0.w, a1.x, a1.y, a1.z, a1.w};
            float br[8] = {b0.x, b0.y, b0.z, b0.w, b1.x, b1.y, b1.z, b1.w};
            #pragma unroll
            for (int i = 0; i < 8; ++i)
                #pragma unroll
                for (int j = 0; j < 8; ++j) acc[i][j] += ar[i] * br[j];
        }
        __syncthreads();
    }
    #pragma unroll
    for (int i = 0; i < 8; ++i) {
        int r = bm + ((i < 4) ? (ty * 4 + i) : (64 + ty * 4 + i - 4));
        if (r < M_ROWS) {
            #pragma unroll
            for (int j = 0; j < 8; ++j) {
                int c = bn + ((j < 4) ? (tx * 4 + j) : (64 + tx * 4 + j - 4));
                g_kv[r * D_MODEL + c] = acc[i][j] + bias[c];
            }
        }
    }
}

// ---------------- kernel 3: in-place LN over g_kv rows ------------------------
__global__ void kvln_kernel(const float* __restrict__ lw, const float* __restrict__ lb) {
    int row = blockIdx.x;
    int t = threadIdx.x;
    float* x = g_kv + row * D_MODEL;
    float v0 = x[t], v1 = x[t + 256], v2 = x[t + 512];
    __shared__ float red[256];
    red[t] = v0 + v1 + v2;
    __syncthreads();
    for (int s = 128; s > 0; s >>= 1) { if (t < s) red[t] += red[t + s]; __syncthreads(); }
    float mean = red[0] * (1.0f / D_MODEL);
    __syncthreads();
    float d0 = v0 - mean, d1 = v1 - mean, d2 = v2 - mean;
    red[t] = d0 * d0 + d1 * d1 + d2 * d2;
    __syncthreads();
    for (int s = 128; s > 0; s >>= 1) { if (t < s) red[t] += red[t + s]; __syncthreads(); }
    float rstd = rsqrtf(red[0] * (1.0f / D_MODEL) + LN_EPS);
    x[t]       = d0 * rstd * lw[t]       + lb[t];
    x[t + 256] = d1 * rstd * lw[t + 256] + lb[t + 256];
    x[t + 512] = d2 * rstd * lw[t + 512] + lb[t + 512];
}

// ---------------- kernel 4 (fused): scores+softmax+A+out-proj per (b,h,half) --
// dynamic smem: tile[P_TOK][TILE_LD] = kv_head + pos_head
extern __shared__ float sm_tile[];
__global__ __launch_bounds__(256) void attn_kernel(const float* __restrict__ pos,
                                                   const float* __restrict__ outw) {
    int b = blockIdx.x, h = blockIdx.y, half = blockIdx.z;
    int tid = threadIdx.x;
    int w = tid >> 5, lane = tid & 31;

    __shared__ float qh[NQ][D_HEAD];
    __shared__ float e[NQ][P_TOK];
    __shared__ float Ash[NQ][D_HEAD];

    // load tile = kv[b,:,h] + pos[half,:,h]  (coalesced 128B rows)
    for (int idx = tid; idx < P_TOK * D_HEAD; idx += 256) {
        int p = idx >> 6, d = idx & 63;
        sm_tile[p * TILE_LD + d] =
            g_kv[(b * P_TOK + p) * D_MODEL + h * D_HEAD + d] +
            pos[(half * P_TOK + p) * D_MODEL + h * D_HEAD + d];
    }
    // load q head slice
    for (int idx = tid; idx < NQ * D_HEAD; idx += 256) {
        int q = idx >> 6, d = idx & 63;
        qh[q][d] = g_qln[q * D_MODEL + h * D_HEAD + d];
    }
    __syncthreads();

    // scores + softmax stats: one warp per q. tile stride 67 -> conflict-free.
    {
        int q = w;
        float mx = -1e30f;
        for (int p = lane; p < P_TOK; p += 32) {
            const float* tp = sm_tile + p * TILE_LD;
            float s = 0.0f;
            #pragma unroll 16
            for (int d = 0; d < D_HEAD; ++d) s += tp[d] * qh[q][d];
            s *= 0.125f;
            e[q][p] = s;
            mx = fmaxf(mx, s);
        }
        #pragma unroll
        for (int off = 16; off > 0; off >>= 1) mx = fmaxf(mx, __shfl_xor_sync(0xffffffffu, mx, off));
        float sum = 0.0f;
        for (int p = lane; p < P_TOK; p += 32) {
            float t = __expf(e[q][p] - mx);
            e[q][p] = t;
            sum += t;
        }
        #pragma unroll
        for (int off = 16; off > 0; off >>= 1) sum += __shfl_xor_sync(0xffffffffu, sum, off);
        if (lane == 0) {
            int idx = ((half * BATCH + b) * NUM_HEADS + h) * NQ + q;
            g_m[idx] = mx;
            g_z[idx] = sum;
        }
    }
    __syncthreads();

    // A[q][d] = sum_p e[q][p] * tile[p][d]   (e broadcast, tile coalesced)
    for (int ii = tid; ii < NQ * D_HEAD; ii += 256) {
        int q = ii >> 6, d = ii & 63;
        float acc = 0.0f;
        #pragma unroll 4
        for (int p = 0; p < P_TOK; ++p) acc += e[q][p] * sm_tile[p * TILE_LD + d];
        Ash[q][d] = acc;
    }
    __syncthreads();

    // P[q][o] = sum_d A[q][d] * out_w[o, h*64+d]  -> g_p
    long pbase = (long)(((half * BATCH + b) * NUM_HEADS + h) * NQ) * D_MODEL;
    for (int o = tid; o < D_MODEL; o += 256) {
        const float4* wr = (const float4*)(outw + o * D_MODEL + h * D_HEAD);
        float acc[NQ];
        #pragma unroll
        for (int q = 0; q < NQ; ++q) acc[q] = 0.0f;
        #pragma unroll
        for (int d4 = 0; d4 < D_HEAD / 4; ++d4) {
            float4 wv = wr[d4];
            int d = d4 * 4;
            #pragma unroll
            for (int q = 0; q < NQ; ++q) {
                acc[q] += Ash[q][d] * wv.x + Ash[q][d + 1] * wv.y +
                          Ash[q][d + 2] * wv.z + Ash[q][d + 3] * wv.w;
            }
        }
        #pragma unroll
        for (int q = 0; q < NQ; ++q)
            g_p[pbase + q * D_MODEL + o] = acc[q];
    }
}

// ---------------- kernel 5: per-pair softmax merge + combine (float4) ---------
__global__ __launch_bounds__(192) void combine_kernel(const float* __restrict__ outb,
                                                      float* __restrict__ out) {
    int pair = blockIdx.x;
    int q = blockIdx.y;
    int i = pair >> 4, j = pair & 15;
    int tid = threadIdx.x;
    __shared__ float c1[NUM_HEADS], c2[NUM_HEADS];
    if (tid < NUM_HEADS) {
        int h = tid;
        int i1 = (i * NUM_HEADS + h) * NQ + q;
        int i2 = ((BATCH + j) * NUM_HEADS + h) * NQ + q;
        float m1 = g_m[i1], m2 = g_m[i2];
        float z1 = g_z[i1], z2 = g_z[i2];
        float m = fmaxf(m1, m2);
        float e1 = __expf(m1 - m), e2 = __expf(m2 - m);
        float zinv = 1.0f / (e1 * z1 + e2 * z2);
        c1[h] = e1 * zinv;
        c2[h] = e2 * zinv;
    }
    __syncthreads();
    int o4 = tid;  // 0..191, 768/4
    float4 acc = ((const float4*)outb)[o4];
    #pragma unroll
    for (int h = 0; h < NUM_HEADS; ++h) {
        const float4* p1 = (const float4*)(g_p + (long)((i * NUM_HEADS + h) * NQ + q) * D_MODEL);
        const float4* p2 = (const float4*)(g_p + (long)(((BATCH + j) * NUM_HEADS + h) * NQ + q) * D_MODEL);
        float4 a = p1[o4], bb = p2[o4];
        float w1 = c1[h], w2 = c2[h];
        acc.x += w1 * a.x - w2 * bb.x;
        acc.y += w1 * a.y - w2 * bb.y;
        acc.z += w1 * a.z - w2 * bb.z;
        acc.w += w1 * a.w - w2 * bb.w;
    }
    ((float4*)out)[(long)(pair * NQ + q) * (D_MODEL / 4) + o4] = acc;
}

// ---------------- launch ------------------------------------------------------
extern "C" void kernel_launch(void* const* d_in, const int* in_sizes, int n_in,
                              void* d_out, int out_size) {
    const float* q_x   = (const float*)d_in[0];
    const float* kv_x  = (const float*)d_in[1];
    const float* pos   = (const float*)d_in[2];
    const float* q_w   = (const float*)d_in[3];
    const float* q_b   = (const float*)d_in[4];
    const float* kv_w  = (const float*)d_in[5];
    const float* kv_b  = (const float*)d_in[6];
    const float* out_w = (const float*)d_in[7];
    const float* out_b = (const float*)d_in[8];
    const float* lnq_w = (const float*)d_in[9];
    const float* lnq_b = (const float*)d_in[10];
    const float* lnkv_w = (const float*)d_in[11];
    const float* lnkv_b = (const float*)d_in[12];
    float* out = (float*)d_out;

    static bool attr_set = false;
    int tile_bytes = P_TOK * TILE_LD * sizeof(float);  // 52796 B
    if (!attr_set) {
        cudaFuncSetAttribute(attn_kernel, cudaFuncAttributeMaxDynamicSharedMemorySize, tile_bytes);
        attr_set = true;
    }

    qproj_kernel<<<NQ, D_MODEL>>>(q_x, q_w, q_b, lnq_w, lnq_b);
    kv_gemm_kernel<<<dim3(D_MODEL / 128, (M_ROWS + 127) / 128), 256>>>(kv_x, kv_w, kv_b);
    kvln_kernel<<<M_ROWS, 256>>>(lnkv_w, lnkv_b);
    attn_kernel<<<dim3(BATCH, NUM_HEADS, 2), 256, tile_bytes>>>(pos, out_w);
    combine_kernel<<<dim3(PAIRS, NQ), 192>>>(out_b, out);
}

// round 5
// speedup vs baseline: 4.0999x; 3.9044x over previous
#include <cuda_runtime.h>
#include <cuda_bf16.h>
#include <cstdint>
#include <math.h>

#define D_MODEL 768
#define NUM_HEADS 12
#define D_HEAD 64
#define NQ 8
#define BATCH 16
#define P_TOK 197
#define M_ROWS (BATCH * P_TOK)       // 3152
#define M_PAD 3200                   // 25 * 128
#define PAIRS (BATCH * BATCH)        // 256
#define OUT_ROWS (PAIRS * NQ)        // 2048 = 16 * 128
#define LN_EPS 1e-5f
#define TILE_LD 67

// GEMM tiling
#define BM 128
#define BN 128
#define BK 32
#define LDA 40                       // bf16 elems per smem row (80B stride)
#define MAT_B (128 * LDA * 2)        // 10240 bytes per matrix
#define STAGE_B (4 * MAT_B)          // 40960 bytes per stage

// ---------------- scratch (device globals) ------------------------------------
__device__ float g_qpre[NQ * D_MODEL];
__device__ float g_qln[NQ * D_MODEL];
__device__ float g_kv[M_ROWS * D_MODEL];
__device__ __nv_bfloat16 g_xh[M_PAD * D_MODEL];
__device__ __nv_bfloat16 g_xl[M_PAD * D_MODEL];
__device__ __nv_bfloat16 g_wh[D_MODEL * D_MODEL];
__device__ __nv_bfloat16 g_wl[D_MODEL * D_MODEL];
__device__ __nv_bfloat16 g_owh[D_MODEL * D_MODEL];
__device__ __nv_bfloat16 g_owl[D_MODEL * D_MODEL];
__device__ __nv_bfloat16 g_ach[OUT_ROWS * D_MODEL];
__device__ __nv_bfloat16 g_acl[OUT_ROWS * D_MODEL];
__device__ float g_m[2 * BATCH * NUM_HEADS * NQ];
__device__ float g_z[2 * BATCH * NUM_HEADS * NQ];
__device__ float g_a[2 * BATCH * NUM_HEADS * NQ * D_HEAD];

// ---------------- PTX helpers (family-portable only) --------------------------
__device__ __forceinline__ uint32_t smem_u32(const void* p) {
    uint32_t a;
    asm("{ .reg .u64 t; cvta.to.shared.u64 t, %1; cvt.u32.u64 %0, t; }" : "=r"(a) : "l"(p));
    return a;
}
__device__ __forceinline__ void cp_async16(uint32_t s, const void* g) {
    asm volatile("cp.async.cg.shared.global [%0], [%1], 16;" :: "r"(s), "l"(g));
}
#define CP_COMMIT() asm volatile("cp.async.commit_group;")
#define CP_WAIT(n)  asm volatile("cp.async.wait_group %0;" :: "n"(n))
#define LDMX4(r, addr) \
    asm volatile("ldmatrix.sync.aligned.m8n8.x4.shared.b16 {%0,%1,%2,%3}, [%4];" \
        : "=r"((r)[0]), "=r"((r)[1]), "=r"((r)[2]), "=r"((r)[3]) : "r"(addr))
#define MMA_BF16(cr, a, b0, b1) \
    asm volatile("mma.sync.aligned.m16n8k16.row.col.f32.bf16.bf16.f32 " \
        "{%0,%1,%2,%3}, {%4,%5,%6,%7}, {%8,%9}, {%0,%1,%2,%3};" \
        : "+f"((cr)[0]), "+f"((cr)[1]), "+f"((cr)[2]), "+f"((cr)[3]) \
        : "r"((a)[0]), "r"((a)[1]), "r"((a)[2]), "r"((a)[3]), "r"(b0), "r"(b1))

// ---------------- split kernels: fp32 -> (bf16 hi, bf16 lo) -------------------
__global__ void splitx_kernel(const float* __restrict__ x) {
    int i4 = blockIdx.x * blockDim.x + threadIdx.x;   // float4 index
    int row = i4 / (D_MODEL / 4);
    float4 v;
    if (row < M_ROWS) v = ((const float4*)x)[i4];
    else v = make_float4(0.f, 0.f, 0.f, 0.f);
    __nv_bfloat16 hx = __float2bfloat16_rn(v.x);
    __nv_bfloat16 hy = __float2bfloat16_rn(v.y);
    __nv_bfloat16 hz = __float2bfloat16_rn(v.z);
    __nv_bfloat16 hw = __float2bfloat16_rn(v.w);
    ushort4 hi = make_ushort4(__bfloat16_as_ushort(hx), __bfloat16_as_ushort(hy),
                              __bfloat16_as_ushort(hz), __bfloat16_as_ushort(hw));
    ushort4 lo = make_ushort4(
        __bfloat16_as_ushort(__float2bfloat16_rn(v.x - __bfloat162float(hx))),
        __bfloat16_as_ushort(__float2bfloat16_rn(v.y - __bfloat162float(hy))),
        __bfloat16_as_ushort(__float2bfloat16_rn(v.z - __bfloat162float(hz))),
        __bfloat16_as_ushort(__float2bfloat16_rn(v.w - __bfloat162float(hw))));
    ((ushort4*)g_xh)[i4] = hi;
    ((ushort4*)g_xl)[i4] = lo;
}
__global__ void splitw_kernel(const float* __restrict__ w,
                              __nv_bfloat16* __restrict__ dh,
                              __nv_bfloat16* __restrict__ dl) {
    int i4 = blockIdx.x * blockDim.x + threadIdx.x;
    float4 v = ((const float4*)w)[i4];
    __nv_bfloat16 hx = __float2bfloat16_rn(v.x);
    __nv_bfloat16 hy = __float2bfloat16_rn(v.y);
    __nv_bfloat16 hz = __float2bfloat16_rn(v.z);
    __nv_bfloat16 hw = __float2bfloat16_rn(v.w);
    ushort4 hi = make_ushort4(__bfloat16_as_ushort(hx), __bfloat16_as_ushort(hy),
                              __bfloat16_as_ushort(hz), __bfloat16_as_ushort(hw));
    ushort4 lo = make_ushort4(
        __bfloat16_as_ushort(__float2bfloat16_rn(v.x - __bfloat162float(hx))),
        __bfloat16_as_ushort(__float2bfloat16_rn(v.y - __bfloat162float(hy))),
        __bfloat16_as_ushort(__float2bfloat16_rn(v.z - __bfloat162float(hz))),
        __bfloat16_as_ushort(__float2bfloat16_rn(v.w - __bfloat162float(hw))));
    ((ushort4*)dh)[i4] = hi;
    ((ushort4*)dl)[i4] = lo;
}

// ---------------- tensor-core GEMM: C[M,768] = A @ B^T + bias ----------------
// A, B given as bf16 (hi, lo) pairs; fp32 accumulate of Ah*Bh + Ah*Bl + Al*Bh.
// Block 128x128, BK=32, 256 threads (8 warps: 4 M x 2 N), cp.async 2-stage.
__global__ __launch_bounds__(256) void gemm_bf16(
    const __nv_bfloat16* __restrict__ Agh, const __nv_bfloat16* __restrict__ Agl,
    const __nv_bfloat16* __restrict__ Bgh, const __nv_bfloat16* __restrict__ Bgl,
    const float* __restrict__ bias, float* __restrict__ C, int Mvalid) {
    extern __shared__ char sm[];
    uint32_t sbase = smem_u32(sm);
    int tid = threadIdx.x, lane = tid & 31, wid = tid >> 5;
    int wm = wid & 3, wn = wid >> 2;
    int bm = blockIdx.y * BM, bn = blockIdx.x * BN;

    float c[2][8][4];
    #pragma unroll
    for (int i = 0; i < 2; ++i)
        #pragma unroll
        for (int j = 0; j < 8; ++j)
            #pragma unroll
            for (int k = 0; k < 4; ++k) c[i][j][k] = 0.0f;

    int lrow = tid >> 2, lc = tid & 3;   // 64 rows per pass x 4 chunks

    auto ld_stage = [&](int kc, int s) {
        uint32_t st = sbase + s * STAGE_B;
        #pragma unroll
        for (int t = 0; t < 2; ++t) {
            int row = lrow + t * 64;
            uint32_t doff = (uint32_t)(row * 80 + lc * 16);
            size_t ga = (size_t)(bm + row) * D_MODEL + kc * BK + lc * 8;
            size_t gb = (size_t)(bn + row) * D_MODEL + kc * BK + lc * 8;
            cp_async16(st + doff,             Agh + ga);
            cp_async16(st + MAT_B + doff,     Agl + ga);
            cp_async16(st + 2 * MAT_B + doff, Bgh + gb);
            cp_async16(st + 3 * MAT_B + doff, Bgl + gb);
        }
    };

    auto compute = [&](int s) {
        uint32_t st = sbase + s * STAGE_B;
        int arow = ((lane >> 3) & 1) * 8 + (lane & 7);
        int acolb = (lane >> 4) * 8;
        int brow = (lane >> 4) * 8 + (lane & 7);
        int bcolb = ((lane >> 3) & 1) * 8;
        #pragma unroll
        for (int ks = 0; ks < 2; ++ks) {
            uint32_t ah[2][4], al[2][4], bh[4][4], bl[4][4];
            #pragma unroll
            for (int mt = 0; mt < 2; ++mt) {
                uint32_t ad = st + (uint32_t)((wm * 32 + mt * 16 + arow) * 80 +
                                              (ks * 16 + acolb) * 2);
                LDMX4(ah[mt], ad);
                LDMX4(al[mt], ad + MAT_B);
            }
            #pragma unroll
            for (int nt2 = 0; nt2 < 4; ++nt2) {
                uint32_t bd = st + 2 * MAT_B + (uint32_t)((wn * 64 + nt2 * 16 + brow) * 80 +
                                                          (ks * 16 + bcolb) * 2);
                LDMX4(bh[nt2], bd);
                LDMX4(bl[nt2], bd + MAT_B);
            }
            #pragma unroll
            for (int mt = 0; mt < 2; ++mt)
                #pragma unroll
                for (int nt = 0; nt < 8; ++nt) {
                    int n2 = nt >> 1, pr = (nt & 1) * 2;
                    MMA_BF16(c[mt][nt], ah[mt], bh[n2][pr], bh[n2][pr + 1]);
                    MMA_BF16(c[mt][nt], ah[mt], bl[n2][pr], bl[n2][pr + 1]);
                    MMA_BF16(c[mt][nt], al[mt], bh[n2][pr], bh[n2][pr + 1]);
                }
        }
    };

    ld_stage(0, 0);
    CP_COMMIT();
    const int KC = D_MODEL / BK;   // 24
    for (int kc = 0; kc < KC; ++kc) {
        int s = kc & 1;
        if (kc < KC - 1) {
            ld_stage(kc + 1, s ^ 1);
            CP_COMMIT();
            CP_WAIT(1);
        } else {
            CP_WAIT(0);
        }
        __syncthreads();
        compute(s);
        __syncthreads();
    }

    // epilogue
    #pragma unroll
    for (int mt = 0; mt < 2; ++mt) {
        int r0 = bm + wm * 32 + mt * 16 + (lane >> 2);
        #pragma unroll
        for (int nt = 0; nt < 8; ++nt) {
            int col = bn + wn * 64 + nt * 8 + (lane & 3) * 2;
            float b0 = bias[col], b1 = bias[col + 1];
            if (r0 < Mvalid) {
                C[(size_t)r0 * D_MODEL + col]     = c[mt][nt][0] + b0;
                C[(size_t)r0 * D_MODEL + col + 1] = c[mt][nt][1] + b1;
            }
            if (r0 + 8 < Mvalid) {
                C[(size_t)(r0 + 8) * D_MODEL + col]     = c[mt][nt][2] + b0;
                C[(size_t)(r0 + 8) * D_MODEL + col + 1] = c[mt][nt][3] + b1;
            }
        }
    }
}

// ---------------- q path: GEMM then LN ---------------------------------------
__global__ __launch_bounds__(128) void qgemm_kernel(const float* __restrict__ qx,
                                                    const float* __restrict__ qw,
                                                    const float* __restrict__ qb) {
    int row = blockIdx.y;
    int col = blockIdx.x * 128 + threadIdx.x;
    __shared__ float xs[D_MODEL];
    for (int i = threadIdx.x; i < D_MODEL; i += 128) xs[i] = qx[row * D_MODEL + i];
    __syncthreads();
    const float4* wr = (const float4*)(qw + (size_t)col * D_MODEL);
    float acc = qb[col];
    #pragma unroll 8
    for (int k4 = 0; k4 < D_MODEL / 4; ++k4) {
        float4 w = wr[k4];
        const float* x = xs + k4 * 4;
        acc += x[0] * w.x + x[1] * w.y + x[2] * w.z + x[3] * w.w;
    }
    g_qpre[row * D_MODEL + col] = acc;
}
__global__ void qln_kernel(const float* __restrict__ lw, const float* __restrict__ lb) {
    int row = blockIdx.x;
    int t = threadIdx.x;
    const float* x = g_qpre + row * D_MODEL;
    float v0 = x[t], v1 = x[t + 256], v2 = x[t + 512];
    __shared__ float red[256];
    red[t] = v0 + v1 + v2;
    __syncthreads();
    for (int s = 128; s > 0; s >>= 1) { if (t < s) red[t] += red[t + s]; __syncthreads(); }
    float mean = red[0] * (1.0f / D_MODEL);
    __syncthreads();
    float d0 = v0 - mean, d1 = v1 - mean, d2 = v2 - mean;
    red[t] = d0 * d0 + d1 * d1 + d2 * d2;
    __syncthreads();
    for (int s = 128; s > 0; s >>= 1) { if (t < s) red[t] += red[t + s]; __syncthreads(); }
    float rstd = rsqrtf(red[0] * (1.0f / D_MODEL) + LN_EPS);
    g_qln[row * D_MODEL + t]       = d0 * rstd * lw[t]       + lb[t];
    g_qln[row * D_MODEL + t + 256] = d1 * rstd * lw[t + 256] + lb[t + 256];
    g_qln[row * D_MODEL + t + 512] = d2 * rstd * lw[t + 512] + lb[t + 512];
}

// ---------------- in-place LN over g_kv rows ----------------------------------
__global__ void kvln_kernel(const float* __restrict__ lw, const float* __restrict__ lb) {
    int row = blockIdx.x;
    int t = threadIdx.x;
    float* x = g_kv + (size_t)row * D_MODEL;
    float v0 = x[t], v1 = x[t + 256], v2 = x[t + 512];
    __shared__ float red[256];
    red[t] = v0 + v1 + v2;
    __syncthreads();
    for (int s = 128; s > 0; s >>= 1) { if (t < s) red[t] += red[t + s]; __syncthreads(); }
    float mean = red[0] * (1.0f / D_MODEL);
    __syncthreads();
    float d0 = v0 - mean, d1 = v1 - mean, d2 = v2 - mean;
    red[t] = d0 * d0 + d1 * d1 + d2 * d2;
    __syncthreads();
    for (int s = 128; s > 0; s >>= 1) { if (t < s) red[t] += red[t + s]; __syncthreads(); }
    float rstd = rsqrtf(red[0] * (1.0f / D_MODEL) + LN_EPS);
    x[t]       = d0 * rstd * lw[t]       + lb[t];
    x[t + 256] = d1 * rstd * lw[t + 256] + lb[t + 256];
    x[t + 512] = d2 * rstd * lw[t + 512] + lb[t + 512];
}

// ---------------- attention-lite: scores + softmax + A per (b,h,half) ---------
__global__ __launch_bounds__(256) void attn_kernel(const float* __restrict__ pos) {
    extern __shared__ float sm_tile[];
    int b = blockIdx.x, h = blockIdx.y, half = blockIdx.z;
    int tid = threadIdx.x;
    int w = tid >> 5, lane = tid & 31;

    __shared__ float qh[NQ][D_HEAD];
    __shared__ float e[NQ][P_TOK];

    for (int idx = tid; idx < P_TOK * D_HEAD; idx += 256) {
        int p = idx >> 6, d = idx & 63;
        sm_tile[p * TILE_LD + d] =
            g_kv[(size_t)(b * P_TOK + p) * D_MODEL + h * D_HEAD + d] +
            pos[(size_t)(half * P_TOK + p) * D_MODEL + h * D_HEAD + d];
    }
    for (int idx = tid; idx < NQ * D_HEAD; idx += 256) {
        int q = idx >> 6, d = idx & 63;
        qh[q][d] = g_qln[q * D_MODEL + h * D_HEAD + d];
    }
    __syncthreads();

    {
        int q = w;
        float mx = -1e30f;
        for (int p = lane; p < P_TOK; p += 32) {
            const float* tp = sm_tile + p * TILE_LD;
            float s = 0.0f;
            #pragma unroll 16
            for (int d = 0; d < D_HEAD; ++d) s += tp[d] * qh[q][d];
            s *= 0.125f;
            e[q][p] = s;
            mx = fmaxf(mx, s);
        }
        #pragma unroll
        for (int off = 16; off > 0; off >>= 1) mx = fmaxf(mx, __shfl_xor_sync(0xffffffffu, mx, off));
        float sum = 0.0f;
        for (int p = lane; p < P_TOK; p += 32) {
            float t = __expf(e[q][p] - mx);
            e[q][p] = t;
            sum += t;
        }
        #pragma unroll
        for (int off = 16; off > 0; off >>= 1) sum += __shfl_xor_sync(0xffffffffu, sum, off);
        if (lane == 0) {
            int idx = ((half * BATCH + b) * NUM_HEADS + h) * NQ + q;
            g_m[idx] = mx;
            g_z[idx] = sum;
        }
    }
    __syncthreads();

    // A[q][d] = sum_p e[q][p] * tile[p][d]
    for (int ii = tid; ii < NQ * D_HEAD; ii += 256) {
        int q = ii >> 6, d = ii & 63;
        float acc = 0.0f;
        #pragma unroll 4
        for (int p = 0; p < P_TOK; ++p) acc += e[q][p] * sm_tile[p * TILE_LD + d];
        g_a[((((size_t)half * BATCH + b) * NUM_HEADS + h) * NQ + q) * D_HEAD + d] = acc;
    }
}

// ---------------- merge: Acomb[pair*8+q, h*64+d] = c1*A1 - c2*A2 (bf16 split) --
__global__ __launch_bounds__(192) void merge_kernel() {
    int pair = blockIdx.x;
    int q = blockIdx.y;
    int i = pair >> 4, j = pair & 15;
    int tid = threadIdx.x;
    __shared__ float c1s[NUM_HEADS], c2s[NUM_HEADS];
    if (tid < NUM_HEADS) {
        int h = tid;
        int i1 = (i * NUM_HEADS + h) * NQ + q;
        int i2 = ((BATCH + j) * NUM_HEADS + h) * NQ + q;
        float m1 = g_m[i1], m2 = g_m[i2];
        float z1 = g_z[i1], z2 = g_z[i2];
        float m = fmaxf(m1, m2);
        float e1 = __expf(m1 - m), e2 = __expf(m2 - m);
        float zinv = 1.0f / (e1 * z1 + e2 * z2);
        c1s[h] = e1 * zinv;
        c2s[h] = e2 * zinv;
    }
    __syncthreads();
    int o0 = tid * 4;
    int h = o0 >> 6, d = o0 & 63;
    float4 a1 = *(const float4*)(g_a + ((((size_t)0 * BATCH + i) * NUM_HEADS + h) * NQ + q) * D_HEAD + d);
    float4 a2 = *(const float4*)(g_a + ((((size_t)1 * BATCH + j) * NUM_HEADS + h) * NQ + q) * D_HEAD + d);
    float w1 = c1s[h], w2 = c2s[h];
    float4 v;
    v.x = w1 * a1.x - w2 * a2.x;
    v.y = w1 * a1.y - w2 * a2.y;
    v.z = w1 * a1.z - w2 * a2.z;
    v.w = w1 * a1.w - w2 * a2.w;
    __nv_bfloat16 hx = __float2bfloat16_rn(v.x);
    __nv_bfloat16 hy = __float2bfloat16_rn(v.y);
    __nv_bfloat16 hz = __float2bfloat16_rn(v.z);
    __nv_bfloat16 hw = __float2bfloat16_rn(v.w);
    size_t row = (size_t)pair * NQ + q;
    ushort4 hi = make_ushort4(__bfloat16_as_ushort(hx), __bfloat16_as_ushort(hy),
                              __bfloat16_as_ushort(hz), __bfloat16_as_ushort(hw));
    ushort4 lo = make_ushort4(
        __bfloat16_as_ushort(__float2bfloat16_rn(v.x - __bfloat162float(hx))),
        __bfloat16_as_ushort(__float2bfloat16_rn(v.y - __bfloat162float(hy))),
        __bfloat16_as_ushort(__float2bfloat16_rn(v.z - __bfloat162float(hz))),
        __bfloat16_as_ushort(__float2bfloat16_rn(v.w - __bfloat162float(hw))));
    ((ushort4*)(g_ach + row * D_MODEL))[tid] = hi;
    ((ushort4*)(g_acl + row * D_MODEL))[tid] = lo;
}

// ---------------- launch ------------------------------------------------------
extern "C" void kernel_launch(void* const* d_in, const int* in_sizes, int n_in,
                              void* d_out, int out_size) {
    const float* q_x   = (const float*)d_in[0];
    const float* kv_x  = (const float*)d_in[1];
    const float* pos   = (const float*)d_in[2];
    const float* q_w   = (const float*)d_in[3];
    const float* q_b   = (const float*)d_in[4];
    const float* kv_w  = (const float*)d_in[5];
    const float* kv_b  = (const float*)d_in[6];
    const float* out_w = (const float*)d_in[7];
    const float* out_b = (const float*)d_in[8];
    const float* lnq_w = (const float*)d_in[9];
    const float* lnq_b = (const float*)d_in[10];
    const float* lnkv_w = (const float*)d_in[11];
    const float* lnkv_b = (const float*)d_in[12];
    float* out = (float*)d_out;

    // device-global pointers for the GEMM arguments
    __nv_bfloat16 *p_xh, *p_xl, *p_wh, *p_wl, *p_owh, *p_owl, *p_ach, *p_acl;
    float* p_kv;
    cudaGetSymbolAddress((void**)&p_xh, g_xh);
    cudaGetSymbolAddress((void**)&p_xl, g_xl);
    cudaGetSymbolAddress((void**)&p_wh, g_wh);
    cudaGetSymbolAddress((void**)&p_wl, g_wl);
    cudaGetSymbolAddress((void**)&p_owh, g_owh);
    cudaGetSymbolAddress((void**)&p_owl, g_owl);
    cudaGetSymbolAddress((void**)&p_ach, g_ach);
    cudaGetSymbolAddress((void**)&p_acl, g_acl);
    cudaGetSymbolAddress((void**)&p_kv, g_kv);

    int gemm_smem = 2 * STAGE_B;   // 81920
    cudaFuncSetAttribute(gemm_bf16, cudaFuncAttributeMaxDynamicSharedMemorySize, gemm_smem);
    int tile_bytes = P_TOK * TILE_LD * sizeof(float);
    cudaFuncSetAttribute(attn_kernel, cudaFuncAttributeMaxDynamicSharedMemorySize, tile_bytes);

    splitx_kernel<<<(M_PAD * D_MODEL / 4) / 256, 256>>>(kv_x);
    splitw_kernel<<<(D_MODEL * D_MODEL / 4) / 256, 256>>>(kv_w, p_wh, p_wl);
    splitw_kernel<<<(D_MODEL * D_MODEL / 4) / 256, 256>>>(out_w, p_owh, p_owl);
    qgemm_kernel<<<dim3(6, NQ), 128>>>(q_x, q_w, q_b);
    qln_kernel<<<NQ, 256>>>(lnq_w, lnq_b);
    gemm_bf16<<<dim3(6, 25), 256, gemm_smem>>>(p_xh, p_xl, p_wh, p_wl, kv_b, p_kv, M_ROWS);
    kvln_kernel<<<M_ROWS, 256>>>(lnkv_w, lnkv_b);
    attn_kernel<<<dim3(BATCH, NUM_HEADS, 2), 256, tile_bytes>>>(pos);
    merge_kernel<<<dim3(PAIRS, NQ), 192>>>();
    gemm_bf16<<<dim3(6, 16), 256, gemm_smem>>>(p_ach, p_acl, p_owh, p_owl, out_b, out, OUT_ROWS);
}

// round 6
// speedup vs baseline: 5.0568x; 1.2334x over previous
#include <cuda_runtime.h>
#include <cuda_bf16.h>
#include <cstdint>
#include <math.h>

#define D_MODEL 768
#define NUM_HEADS 12
#define D_HEAD 64
#define NQ 8
#define BATCH 16
#define P_TOK 197
#define M_ROWS (BATCH * P_TOK)       // 3152
#define M_PAD 3200                   // 25 * 128
#define PAIRS (BATCH * BATCH)        // 256
#define OUT_ROWS (PAIRS * NQ)        // 2048
#define LN_EPS 1e-5f
#define TILE_LD 68                   // float4-aligned, conflict-free

// GEMM tiling
#define BM 128
#define BN 128
#define BK 32
#define LDA 40                       // bf16 elems per smem row (80B stride)
#define MAT_B (128 * LDA * 2)        // 10240 bytes per matrix
#define STAGE_B (4 * MAT_B)          // 40960 bytes per stage

// ---------------- scratch (device globals) ------------------------------------
__device__ float g_qpre[NQ * D_MODEL];
__device__ float g_qln[NQ * D_MODEL];
__device__ float g_kv[M_ROWS * D_MODEL];
__device__ float g_mean[M_ROWS];
__device__ float g_rstd[M_ROWS];
__device__ __nv_bfloat16 g_xh[M_PAD * D_MODEL];
__device__ __nv_bfloat16 g_xl[M_PAD * D_MODEL];
__device__ __nv_bfloat16 g_wh[D_MODEL * D_MODEL];
__device__ __nv_bfloat16 g_wl[D_MODEL * D_MODEL];
__device__ __nv_bfloat16 g_owh[D_MODEL * D_MODEL];
__device__ __nv_bfloat16 g_owl[D_MODEL * D_MODEL];
__device__ __nv_bfloat16 g_ach[OUT_ROWS * D_MODEL];
__device__ __nv_bfloat16 g_acl[OUT_ROWS * D_MODEL];
__device__ float g_m[2 * BATCH * NUM_HEADS * NQ];
__device__ float g_z[2 * BATCH * NUM_HEADS * NQ];
__device__ float g_a[2 * BATCH * NUM_HEADS * NQ * D_HEAD];

// ---------------- PTX helpers (family-portable only) --------------------------
__device__ __forceinline__ uint32_t smem_u32(const void* p) {
    uint32_t a;
    asm("{ .reg .u64 t; cvta.to.shared.u64 t, %1; cvt.u32.u64 %0, t; }" : "=r"(a) : "l"(p));
    return a;
}
__device__ __forceinline__ void cp_async16(uint32_t s, const void* g) {
    asm volatile("cp.async.cg.shared.global [%0], [%1], 16;" :: "r"(s), "l"(g));
}
#define CP_COMMIT() asm volatile("cp.async.commit_group;")
#define CP_WAIT(n)  asm volatile("cp.async.wait_group %0;" :: "n"(n))
#define LDMX4(r, addr) \
    asm volatile("ldmatrix.sync.aligned.m8n8.x4.shared.b16 {%0,%1,%2,%3}, [%4];" \
        : "=r"((r)[0]), "=r"((r)[1]), "=r"((r)[2]), "=r"((r)[3]) : "r"(addr))
#define MMA_BF16(cr, a, b0, b1) \
    asm volatile("mma.sync.aligned.m16n8k16.row.col.f32.bf16.bf16.f32 " \
        "{%0,%1,%2,%3}, {%4,%5,%6,%7}, {%8,%9}, {%0,%1,%2,%3};" \
        : "+f"((cr)[0]), "+f"((cr)[1]), "+f"((cr)[2]), "+f"((cr)[3]) \
        : "r"((a)[0]), "r"((a)[1]), "r"((a)[2]), "r"((a)[3]), "r"(b0), "r"(b1))

// ---------------- split kernels: fp32 -> (bf16 hi, bf16 lo) -------------------
__global__ void splitx_kernel(const float* __restrict__ x) {
    int i4 = blockIdx.x * blockDim.x + threadIdx.x;
    int row = i4 / (D_MODEL / 4);
    float4 v;
    if (row < M_ROWS) v = ((const float4*)x)[i4];
    else v = make_float4(0.f, 0.f, 0.f, 0.f);
    __nv_bfloat16 hx = __float2bfloat16_rn(v.x);
    __nv_bfloat16 hy = __float2bfloat16_rn(v.y);
    __nv_bfloat16 hz = __float2bfloat16_rn(v.z);
    __nv_bfloat16 hw = __float2bfloat16_rn(v.w);
    ushort4 hi = make_ushort4(__bfloat16_as_ushort(hx), __bfloat16_as_ushort(hy),
                              __bfloat16_as_ushort(hz), __bfloat16_as_ushort(hw));
    ushort4 lo = make_ushort4(
        __bfloat16_as_ushort(__float2bfloat16_rn(v.x - __bfloat162float(hx))),
        __bfloat16_as_ushort(__float2bfloat16_rn(v.y - __bfloat162float(hy))),
        __bfloat16_as_ushort(__float2bfloat16_rn(v.z - __bfloat162float(hz))),
        __bfloat16_as_ushort(__float2bfloat16_rn(v.w - __bfloat162float(hw))));
    ((ushort4*)g_xh)[i4] = hi;
    ((ushort4*)g_xl)[i4] = lo;
}
__global__ void splitw_kernel(const float* __restrict__ w,
                              __nv_bfloat16* __restrict__ dh,
                              __nv_bfloat16* __restrict__ dl) {
    int i4 = blockIdx.x * blockDim.x + threadIdx.x;
    float4 v = ((const float4*)w)[i4];
    __nv_bfloat16 hx = __float2bfloat16_rn(v.x);
    __nv_bfloat16 hy = __float2bfloat16_rn(v.y);
    __nv_bfloat16 hz = __float2bfloat16_rn(v.z);
    __nv_bfloat16 hw = __float2bfloat16_rn(v.w);
    ushort4 hi = make_ushort4(__bfloat16_as_ushort(hx), __bfloat16_as_ushort(hy),
                              __bfloat16_as_ushort(hz), __bfloat16_as_ushort(hw));
    ushort4 lo = make_ushort4(
        __bfloat16_as_ushort(__float2bfloat16_rn(v.x - __bfloat162float(hx))),
        __bfloat16_as_ushort(__float2bfloat16_rn(v.y - __bfloat162float(hy))),
        __bfloat16_as_ushort(__float2bfloat16_rn(v.z - __bfloat162float(hz))),
        __bfloat16_as_ushort(__float2bfloat16_rn(v.w - __bfloat162float(hw))));
    ((ushort4*)dh)[i4] = hi;
    ((ushort4*)dl)[i4] = lo;
}

// ---------------- tensor-core GEMM: C[M,768] = A @ B^T + bias ----------------
__global__ __launch_bounds__(256) void gemm_bf16(
    const __nv_bfloat16* __restrict__ Agh, const __nv_bfloat16* __restrict__ Agl,
    const __nv_bfloat16* __restrict__ Bgh, const __nv_bfloat16* __restrict__ Bgl,
    const float* __restrict__ bias, float* __restrict__ C, int Mvalid) {
    extern __shared__ char sm[];
    uint32_t sbase = smem_u32(sm);
    int tid = threadIdx.x, lane = tid & 31, wid = tid >> 5;
    int wm = wid & 3, wn = wid >> 2;
    int bm = blockIdx.y * BM, bn = blockIdx.x * BN;

    float c[2][8][4];
    #pragma unroll
    for (int i = 0; i < 2; ++i)
        #pragma unroll
        for (int j = 0; j < 8; ++j)
            #pragma unroll
            for (int k = 0; k < 4; ++k) c[i][j][k] = 0.0f;

    int lrow = tid >> 2, lc = tid & 3;

    auto ld_stage = [&](int kc, int s) {
        uint32_t st = sbase + s * STAGE_B;
        #pragma unroll
        for (int t = 0; t < 2; ++t) {
            int row = lrow + t * 64;
            uint32_t doff = (uint32_t)(row * 80 + lc * 16);
            size_t ga = (size_t)(bm + row) * D_MODEL + kc * BK + lc * 8;
            size_t gb = (size_t)(bn + row) * D_MODEL + kc * BK + lc * 8;
            cp_async16(st + doff,             Agh + ga);
            cp_async16(st + MAT_B + doff,     Agl + ga);
            cp_async16(st + 2 * MAT_B + doff, Bgh + gb);
            cp_async16(st + 3 * MAT_B + doff, Bgl + gb);
        }
    };

    auto compute = [&](int s) {
        uint32_t st = sbase + s * STAGE_B;
        int arow = ((lane >> 3) & 1) * 8 + (lane & 7);
        int acolb = (lane >> 4) * 8;
        int brow = (lane >> 4) * 8 + (lane & 7);
        int bcolb = ((lane >> 3) & 1) * 8;
        #pragma unroll
        for (int ks = 0; ks < 2; ++ks) {
            uint32_t ah[2][4], al[2][4], bh[4][4], bl[4][4];
            #pragma unroll
            for (int mt = 0; mt < 2; ++mt) {
                uint32_t ad = st + (uint32_t)((wm * 32 + mt * 16 + arow) * 80 +
                                              (ks * 16 + acolb) * 2);
                LDMX4(ah[mt], ad);
                LDMX4(al[mt], ad + MAT_B);
            }
            #pragma unroll
            for (int nt2 = 0; nt2 < 4; ++nt2) {
                uint32_t bd = st + 2 * MAT_B + (uint32_t)((wn * 64 + nt2 * 16 + brow) * 80 +
                                                          (ks * 16 + bcolb) * 2);
                LDMX4(bh[nt2], bd);
                LDMX4(bl[nt2], bd + MAT_B);
            }
            #pragma unroll
            for (int mt = 0; mt < 2; ++mt)
                #pragma unroll
                for (int nt = 0; nt < 8; ++nt) {
                    int n2 = nt >> 1, pr = (nt & 1) * 2;
                    MMA_BF16(c[mt][nt], ah[mt], bh[n2][pr], bh[n2][pr + 1]);
                    MMA_BF16(c[mt][nt], ah[mt], bl[n2][pr], bl[n2][pr + 1]);
                    MMA_BF16(c[mt][nt], al[mt], bh[n2][pr], bh[n2][pr + 1]);
                }
        }
    };

    ld_stage(0, 0);
    CP_COMMIT();
    const int KC = D_MODEL / BK;
    for (int kc = 0; kc < KC; ++kc) {
        int s = kc & 1;
        if (kc < KC - 1) {
            ld_stage(kc + 1, s ^ 1);
            CP_COMMIT();
            CP_WAIT(1);
        } else {
            CP_WAIT(0);
        }
        __syncthreads();
        compute(s);
        __syncthreads();
    }

    #pragma unroll
    for (int mt = 0; mt < 2; ++mt) {
        int r0 = bm + wm * 32 + mt * 16 + (lane >> 2);
        #pragma unroll
        for (int nt = 0; nt < 8; ++nt) {
            int col = bn + wn * 64 + nt * 8 + (lane & 3) * 2;
            float b0 = bias[col], b1 = bias[col + 1];
            if (r0 < Mvalid) {
                C[(size_t)r0 * D_MODEL + col]     = c[mt][nt][0] + b0;
                C[(size_t)r0 * D_MODEL + col + 1] = c[mt][nt][1] + b1;
            }
            if (r0 + 8 < Mvalid) {
                C[(size_t)(r0 + 8) * D_MODEL + col]     = c[mt][nt][2] + b0;
                C[(size_t)(r0 + 8) * D_MODEL + col + 1] = c[mt][nt][3] + b1;
            }
        }
    }
}

// ---------------- q GEMM: warp per output -------------------------------------
__global__ __launch_bounds__(256) void qgemm_kernel(const float* __restrict__ qx,
                                                    const float* __restrict__ qw,
                                                    const float* __restrict__ qb) {
    int gw = blockIdx.x * 8 + (threadIdx.x >> 5);    // 0..6143
    int lane = threadIdx.x & 31;
    int row = gw / D_MODEL, col = gw - row * D_MODEL;
    const float4* x4 = (const float4*)(qx + (size_t)row * D_MODEL);
    const float4* w4 = (const float4*)(qw + (size_t)col * D_MODEL);
    float acc = 0.0f;
    #pragma unroll
    for (int i = 0; i < 6; ++i) {
        float4 a = x4[lane + 32 * i];
        float4 b = w4[lane + 32 * i];
        acc += a.x * b.x + a.y * b.y + a.z * b.z + a.w * b.w;
    }
    #pragma unroll
    for (int off = 16; off > 0; off >>= 1) acc += __shfl_xor_sync(0xffffffffu, acc, off);
    if (lane == 0) g_qpre[row * D_MODEL + col] = acc + qb[col];
}
__global__ void qln_kernel(const float* __restrict__ lw, const float* __restrict__ lb) {
    int row = blockIdx.x;
    int t = threadIdx.x;
    const float* x = g_qpre + row * D_MODEL;
    float v0 = x[t], v1 = x[t + 256], v2 = x[t + 512];
    __shared__ float red[256];
    red[t] = v0 + v1 + v2;
    __syncthreads();
    for (int s = 128; s > 0; s >>= 1) { if (t < s) red[t] += red[t + s]; __syncthreads(); }
    float mean = red[0] * (1.0f / D_MODEL);
    __syncthreads();
    float d0 = v0 - mean, d1 = v1 - mean, d2 = v2 - mean;
    red[t] = d0 * d0 + d1 * d1 + d2 * d2;
    __syncthreads();
    for (int s = 128; s > 0; s >>= 1) { if (t < s) red[t] += red[t + s]; __syncthreads(); }
    float rstd = rsqrtf(red[0] * (1.0f / D_MODEL) + LN_EPS);
    g_qln[row * D_MODEL + t]       = d0 * rstd * lw[t]       + lb[t];
    g_qln[row * D_MODEL + t + 256] = d1 * rstd * lw[t + 256] + lb[t + 256];
    g_qln[row * D_MODEL + t + 512] = d2 * rstd * lw[t + 512] + lb[t + 512];
}

// ---------------- kv LN stats: warp per row (one pass) ------------------------
__global__ __launch_bounds__(256) void lnstats_kernel() {
    int row = blockIdx.x * 8 + (threadIdx.x >> 5);
    if (row >= M_ROWS) return;
    int lane = threadIdx.x & 31;
    const float4* x4 = (const float4*)(g_kv + (size_t)row * D_MODEL);
    float s1 = 0.0f, s2 = 0.0f;
    #pragma unroll
    for (int i = 0; i < 6; ++i) {
        float4 v = x4[lane + 32 * i];
        s1 += v.x + v.y + v.z + v.w;
        s2 += v.x * v.x + v.y * v.y + v.z * v.z + v.w * v.w;
    }
    #pragma unroll
    for (int off = 16; off > 0; off >>= 1) {
        s1 += __shfl_xor_sync(0xffffffffu, s1, off);
        s2 += __shfl_xor_sync(0xffffffffu, s2, off);
    }
    if (lane == 0) {
        float mean = s1 * (1.0f / D_MODEL);
        float var = s2 * (1.0f / D_MODEL) - mean * mean;
        g_mean[row] = mean;
        g_rstd[row] = rsqrtf(var + LN_EPS);
    }
}

// ---------------- attention: scores + softmax + A per (b,h,half) --------------
// applies kv LN on the fly during tile build.
__global__ __launch_bounds__(256) void attn_kernel(const float* __restrict__ pos,
                                                   const float* __restrict__ lw,
                                                   const float* __restrict__ lb) {
    extern __shared__ float sm_tile[];   // [P_TOK][TILE_LD]
    int b = blockIdx.x, h = blockIdx.y, half = blockIdx.z;
    int tid = threadIdx.x;
    int w = tid >> 5, lane = tid & 31;

    __shared__ float4 qh4[NQ][D_HEAD / 4];
    __shared__ float e[NQ][200];          // rows 16B-aligned

    // tile build: (raw - mean)*rstd*lw + lb + pos, float4 over d
    const float4* lw4 = (const float4*)(lw + h * D_HEAD);
    const float4* lb4 = (const float4*)(lb + h * D_HEAD);
    for (int idx = tid; idx < P_TOK * (D_HEAD / 4); idx += 256) {
        int p = idx >> 4, d4 = idx & 15;
        int row = b * P_TOK + p;
        float m = g_mean[row], r = g_rstd[row];
        float4 raw = ((const float4*)(g_kv + (size_t)row * D_MODEL + h * D_HEAD))[d4];
        float4 pv = ((const float4*)(pos + (size_t)(half * P_TOK + p) * D_MODEL + h * D_HEAD))[d4];
        float4 wv = lw4[d4], bv = lb4[d4];
        float4 out;
        out.x = (raw.x - m) * r * wv.x + bv.x + pv.x;
        out.y = (raw.y - m) * r * wv.y + bv.y + pv.y;
        out.z = (raw.z - m) * r * wv.z + bv.z + pv.z;
        out.w = (raw.w - m) * r * wv.w + bv.w + pv.w;
        *(float4*)(sm_tile + p * TILE_LD + d4 * 4) = out;
    }
    for (int idx = tid; idx < NQ * (D_HEAD / 4); idx += 256) {
        int q = idx >> 4, d4 = idx & 15;
        qh4[q][d4] = ((const float4*)(g_qln + q * D_MODEL + h * D_HEAD))[d4];
    }
    __syncthreads();

    // scores + softmax stats: one warp per q, float4 dots
    {
        int q = w;
        float mx = -1e30f;
        for (int p = lane; p < P_TOK; p += 32) {
            const float4* tp4 = (const float4*)(sm_tile + p * TILE_LD);
            float s = 0.0f;
            #pragma unroll
            for (int k = 0; k < D_HEAD / 4; ++k) {
                float4 t = tp4[k];
                float4 qv = qh4[q][k];
                s += t.x * qv.x + t.y * qv.y + t.z * qv.z + t.w * qv.w;
            }
            s *= 0.125f;
            e[q][p] = s;
            mx = fmaxf(mx, s);
        }
        #pragma unroll
        for (int off = 16; off > 0; off >>= 1) mx = fmaxf(mx, __shfl_xor_sync(0xffffffffu, mx, off));
        float sum = 0.0f;
        for (int p = lane; p < P_TOK; p += 32) {
            float t = __expf(e[q][p] - mx);
            e[q][p] = t;
            sum += t;
        }
        #pragma unroll
        for (int off = 16; off > 0; off >>= 1) sum += __shfl_xor_sync(0xffffffffu, sum, off);
        if (lane == 0) {
            int idx = ((half * BATCH + b) * NUM_HEADS + h) * NQ + q;
            g_m[idx] = mx;
            g_z[idx] = sum;
        }
    }
    __syncthreads();

    // A[q][d] = sum_p e[q][p] * tile[p][d], unroll 4 over p with float4 e
    for (int ii = tid; ii < NQ * D_HEAD; ii += 256) {
        int q = ii >> 6, d = ii & 63;
        float acc = 0.0f;
        const float* tcol = sm_tile + d;
        #pragma unroll 4
        for (int p = 0; p < 196; p += 4) {
            float4 ev = *(const float4*)&e[q][p];
            acc += ev.x * tcol[p * TILE_LD] + ev.y * tcol[(p + 1) * TILE_LD] +
                   ev.z * tcol[(p + 2) * TILE_LD] + ev.w * tcol[(p + 3) * TILE_LD];
        }
        acc += e[q][196] * tcol[196 * TILE_LD];
        g_a[((((size_t)half * BATCH + b) * NUM_HEADS + h) * NQ + q) * D_HEAD + d] = acc;
    }
}

// ---------------- merge: Acomb = c1*A1 - c2*A2 (bf16 split) -------------------
__global__ __launch_bounds__(192) void merge_kernel() {
    int pair = blockIdx.x;
    int q = blockIdx.y;
    int i = pair >> 4, j = pair & 15;
    int tid = threadIdx.x;
    __shared__ float c1s[NUM_HEADS], c2s[NUM_HEADS];
    if (tid < NUM_HEADS) {
        int h = tid;
        int i1 = (i * NUM_HEADS + h) * NQ + q;
        int i2 = ((BATCH + j) * NUM_HEADS + h) * NQ + q;
        float m1 = g_m[i1], m2 = g_m[i2];
        float z1 = g_z[i1], z2 = g_z[i2];
        float m = fmaxf(m1, m2);
        float e1 = __expf(m1 - m), e2 = __expf(m2 - m);
        float zinv = 1.0f / (e1 * z1 + e2 * z2);
        c1s[h] = e1 * zinv;
        c2s[h] = e2 * zinv;
    }
    __syncthreads();
    int o0 = tid * 4;
    int h = o0 >> 6, d = o0 & 63;
    float4 a1 = *(const float4*)(g_a + ((((size_t)0 * BATCH + i) * NUM_HEADS + h) * NQ + q) * D_HEAD + d);
    float4 a2 = *(const float4*)(g_a + ((((size_t)1 * BATCH + j) * NUM_HEADS + h) * NQ + q) * D_HEAD + d);
    float w1 = c1s[h], w2 = c2s[h];
    float4 v;
    v.x = w1 * a1.x - w2 * a2.x;
    v.y = w1 * a1.y - w2 * a2.y;
    v.z = w1 * a1.z - w2 * a2.z;
    v.w = w1 * a1.w - w2 * a2.w;
    __nv_bfloat16 hx = __float2bfloat16_rn(v.x);
    __nv_bfloat16 hy = __float2bfloat16_rn(v.y);
    __nv_bfloat16 hz = __float2bfloat16_rn(v.z);
    __nv_bfloat16 hw = __float2bfloat16_rn(v.w);
    size_t row = (size_t)pair * NQ + q;
    ushort4 hi = make_ushort4(__bfloat16_as_ushort(hx), __bfloat16_as_ushort(hy),
                              __bfloat16_as_ushort(hz), __bfloat16_as_ushort(hw));
    ushort4 lo = make_ushort4(
        __bfloat16_as_ushort(__float2bfloat16_rn(v.x - __bfloat162float(hx))),
        __bfloat16_as_ushort(__float2bfloat16_rn(v.y - __bfloat162float(hy))),
        __bfloat16_as_ushort(__float2bfloat16_rn(v.z - __bfloat162float(hz))),
        __bfloat16_as_ushort(__float2bfloat16_rn(v.w - __bfloat162float(hw))));
    ((ushort4*)(g_ach + row * D_MODEL))[tid] = hi;
    ((ushort4*)(g_acl + row * D_MODEL))[tid] = lo;
}

// ---------------- launch ------------------------------------------------------
extern "C" void kernel_launch(void* const* d_in, const int* in_sizes, int n_in,
                              void* d_out, int out_size) {
    const float* q_x   = (const float*)d_in[0];
    const float* kv_x  = (const float*)d_in[1];
    const float* pos   = (const float*)d_in[2];
    const float* q_w   = (const float*)d_in[3];
    const float* q_b   = (const float*)d_in[4];
    const float* kv_w  = (const float*)d_in[5];
    const float* kv_b  = (const float*)d_in[6];
    const float* out_w = (const float*)d_in[7];
    const float* out_b = (const float*)d_in[8];
    const float* lnq_w = (const float*)d_in[9];
    const float* lnq_b = (const float*)d_in[10];
    const float* lnkv_w = (const float*)d_in[11];
    const float* lnkv_b = (const float*)d_in[12];
    float* out = (float*)d_out;

    __nv_bfloat16 *p_xh, *p_xl, *p_wh, *p_wl, *p_owh, *p_owl, *p_ach, *p_acl;
    float* p_kv;
    cudaGetSymbolAddress((void**)&p_xh, g_xh);
    cudaGetSymbolAddress((void**)&p_xl, g_xl);
    cudaGetSymbolAddress((void**)&p_wh, g_wh);
    cudaGetSymbolAddress((void**)&p_wl, g_wl);
    cudaGetSymbolAddress((void**)&p_owh, g_owh);
    cudaGetSymbolAddress((void**)&p_owl, g_owl);
    cudaGetSymbolAddress((void**)&p_ach, g_ach);
    cudaGetSymbolAddress((void**)&p_acl, g_acl);
    cudaGetSymbolAddress((void**)&p_kv, g_kv);

    int gemm_smem = 2 * STAGE_B;   // 81920
    cudaFuncSetAttribute(gemm_bf16, cudaFuncAttributeMaxDynamicSharedMemorySize, gemm_smem);
    int tile_bytes = P_TOK * TILE_LD * sizeof(float);  // 53584
    cudaFuncSetAttribute(attn_kernel, cudaFuncAttributeMaxDynamicSharedMemorySize, tile_bytes);

    splitx_kernel<<<(M_PAD * D_MODEL / 4) / 256, 256>>>(kv_x);
    splitw_kernel<<<(D_MODEL * D_MODEL / 4) / 256, 256>>>(kv_w, p_wh, p_wl);
    splitw_kernel<<<(D_MODEL * D_MODEL / 4) / 256, 256>>>(out_w, p_owh, p_owl);
    qgemm_kernel<<<(NQ * D_MODEL) / 8, 256>>>(q_x, q_w, q_b);
    qln_kernel<<<NQ, 256>>>(lnq_w, lnq_b);
    gemm_bf16<<<dim3(6, 25), 256, gemm_smem>>>(p_xh, p_xl, p_wh, p_wl, kv_b, p_kv, M_ROWS);
    lnstats_kernel<<<(M_ROWS + 7) / 8, 256>>>();
    attn_kernel<<<dim3(BATCH, NUM_HEADS, 2), 256, tile_bytes>>>(pos, lnkv_w, lnkv_b);
    merge_kernel<<<dim3(PAIRS, NQ), 192>>>();
    gemm_bf16<<<dim3(6, 16), 256, gemm_smem>>>(p_ach, p_acl, p_owh, p_owl, out_b, out, OUT_ROWS);
}

// round 7
// speedup vs baseline: 5.1698x; 1.0223x over previous
#include <cuda_runtime.h>
#include <cuda_bf16.h>
#include <cstdint>
#include <math.h>

#define D_MODEL 768
#define NUM_HEADS 12
#define D_HEAD 64
#define NQ 8
#define BATCH 16
#define P_TOK 197
#define M_ROWS (BATCH * P_TOK)       // 3152
#define M_PAD 3200                   // 25 * 128
#define PAIRS (BATCH * BATCH)        // 256
#define OUT_ROWS (PAIRS * NQ)        // 2048
#define LN_EPS 1e-5f
#define TILE_LD 68

// GEMM tiling
#define BM 128
#define BN 128
#define BK 32
#define LDA 40
#define MAT_B (128 * LDA * 2)
#define STAGE_B (4 * MAT_B)

#define NX4 (M_PAD * D_MODEL / 4)        // 614400 float4 of kv_x (padded)
#define NW4 (D_MODEL * D_MODEL / 4)      // 147456 float4 of a weight

// ---------------- scratch (device globals) ------------------------------------
__device__ float g_qpre[NQ * D_MODEL];
__device__ float g_qln[NQ * D_MODEL];
__device__ float g_kv[M_ROWS * D_MODEL];
__device__ float g_mean[M_ROWS];
__device__ float g_rstd[M_ROWS];
__device__ __nv_bfloat16 g_xh[M_PAD * D_MODEL];
__device__ __nv_bfloat16 g_xl[M_PAD * D_MODEL];
__device__ __nv_bfloat16 g_wh[D_MODEL * D_MODEL];
__device__ __nv_bfloat16 g_wl[D_MODEL * D_MODEL];
__device__ __nv_bfloat16 g_owh[D_MODEL * D_MODEL];
__device__ __nv_bfloat16 g_owl[D_MODEL * D_MODEL];
__device__ __nv_bfloat16 g_ach[OUT_ROWS * D_MODEL];
__device__ __nv_bfloat16 g_acl[OUT_ROWS * D_MODEL];
__device__ float g_m[2 * BATCH * NUM_HEADS * NQ];
__device__ float g_z[2 * BATCH * NUM_HEADS * NQ];
__device__ float g_a[2 * BATCH * NUM_HEADS * NQ * D_HEAD];

// ---------------- PTX helpers --------------------------------------------------
__device__ __forceinline__ uint32_t smem_u32(const void* p) {
    uint32_t a;
    asm("{ .reg .u64 t; cvta.to.shared.u64 t, %1; cvt.u32.u64 %0, t; }" : "=r"(a) : "l"(p));
    return a;
}
__device__ __forceinline__ void cp_async16(uint32_t s, const void* g) {
    asm volatile("cp.async.cg.shared.global [%0], [%1], 16;" :: "r"(s), "l"(g));
}
#define CP_COMMIT() asm volatile("cp.async.commit_group;")
#define CP_WAIT(n)  asm volatile("cp.async.wait_group %0;" :: "n"(n))
#define LDMX4(r, addr) \
    asm volatile("ldmatrix.sync.aligned.m8n8.x4.shared.b16 {%0,%1,%2,%3}, [%4];" \
        : "=r"((r)[0]), "=r"((r)[1]), "=r"((r)[2]), "=r"((r)[3]) : "r"(addr))
#define MMA_BF16(cr, a, b0, b1) \
    asm volatile("mma.sync.aligned.m16n8k16.row.col.f32.bf16.bf16.f32 " \
        "{%0,%1,%2,%3}, {%4,%5,%6,%7}, {%8,%9}, {%0,%1,%2,%3};" \
        : "+f"((cr)[0]), "+f"((cr)[1]), "+f"((cr)[2]), "+f"((cr)[3]) \
        : "r"((a)[0]), "r"((a)[1]), "r"((a)[2]), "r"((a)[3]), "r"(b0), "r"(b1))

// ---------------- split helpers ------------------------------------------------
__device__ __forceinline__ void split4(float4 v, ushort4& hi, ushort4& lo) {
    __nv_bfloat16 hx = __float2bfloat16_rn(v.x);
    __nv_bfloat16 hy = __float2bfloat16_rn(v.y);
    __nv_bfloat16 hz = __float2bfloat16_rn(v.z);
    __nv_bfloat16 hw = __float2bfloat16_rn(v.w);
    hi = make_ushort4(__bfloat16_as_ushort(hx), __bfloat16_as_ushort(hy),
                      __bfloat16_as_ushort(hz), __bfloat16_as_ushort(hw));
    lo = make_ushort4(
        __bfloat16_as_ushort(__float2bfloat16_rn(v.x - __bfloat162float(hx))),
        __bfloat16_as_ushort(__float2bfloat16_rn(v.y - __bfloat162float(hy))),
        __bfloat16_as_ushort(__float2bfloat16_rn(v.z - __bfloat162float(hz))),
        __bfloat16_as_ushort(__float2bfloat16_rn(v.w - __bfloat162float(hw))));
}

// fused: split kv_x (padded) AND kv_w in one launch
__global__ void split_kv_kernel(const float* __restrict__ x, const float* __restrict__ w) {
    int gi = blockIdx.x * blockDim.x + threadIdx.x;
    ushort4 hi, lo;
    if (gi < NX4) {
        int row = gi / (D_MODEL / 4);
        float4 v = (row < M_ROWS) ? ((const float4*)x)[gi] : make_float4(0.f, 0.f, 0.f, 0.f);
        split4(v, hi, lo);
        ((ushort4*)g_xh)[gi] = hi;
        ((ushort4*)g_xl)[gi] = lo;
    } else {
        int wi = gi - NX4;
        if (wi < NW4) {
            split4(((const float4*)w)[wi], hi, lo);
            ((ushort4*)g_wh)[wi] = hi;
            ((ushort4*)g_wl)[wi] = lo;
        }
    }
}
__global__ void splitw_kernel(const float* __restrict__ w,
                              __nv_bfloat16* __restrict__ dh,
                              __nv_bfloat16* __restrict__ dl) {
    int i4 = blockIdx.x * blockDim.x + threadIdx.x;
    ushort4 hi, lo;
    split4(((const float4*)w)[i4], hi, lo);
    ((ushort4*)dh)[i4] = hi;
    ((ushort4*)dl)[i4] = lo;
}

// ---------------- tensor-core GEMM: C[M,768] = A @ B^T + bias -----------------
__global__ __launch_bounds__(256) void gemm_bf16(
    const __nv_bfloat16* __restrict__ Agh, const __nv_bfloat16* __restrict__ Agl,
    const __nv_bfloat16* __restrict__ Bgh, const __nv_bfloat16* __restrict__ Bgl,
    const float* __restrict__ bias, float* __restrict__ C, int Mvalid) {
    extern __shared__ char sm[];
    uint32_t sbase = smem_u32(sm);
    int tid = threadIdx.x, lane = tid & 31, wid = tid >> 5;
    int wm = wid & 3, wn = wid >> 2;
    int bm = blockIdx.y * BM, bn = blockIdx.x * BN;

    float c[2][8][4];
    #pragma unroll
    for (int i = 0; i < 2; ++i)
        #pragma unroll
        for (int j = 0; j < 8; ++j)
            #pragma unroll
            for (int k = 0; k < 4; ++k) c[i][j][k] = 0.0f;

    int lrow = tid >> 2, lc = tid & 3;

    auto ld_stage = [&](int kc, int s) {
        uint32_t st = sbase + s * STAGE_B;
        #pragma unroll
        for (int t = 0; t < 2; ++t) {
            int row = lrow + t * 64;
            uint32_t doff = (uint32_t)(row * 80 + lc * 16);
            size_t ga = (size_t)(bm + row) * D_MODEL + kc * BK + lc * 8;
            size_t gb = (size_t)(bn + row) * D_MODEL + kc * BK + lc * 8;
            cp_async16(st + doff,             Agh + ga);
            cp_async16(st + MAT_B + doff,     Agl + ga);
            cp_async16(st + 2 * MAT_B + doff, Bgh + gb);
            cp_async16(st + 3 * MAT_B + doff, Bgl + gb);
        }
    };

    auto compute = [&](int s) {
        uint32_t st = sbase + s * STAGE_B;
        int arow = ((lane >> 3) & 1) * 8 + (lane & 7);
        int acolb = (lane >> 4) * 8;
        int brow = (lane >> 4) * 8 + (lane & 7);
        int bcolb = ((lane >> 3) & 1) * 8;
        #pragma unroll
        for (int ks = 0; ks < 2; ++ks) {
            uint32_t ah[2][4], al[2][4], bh[4][4], bl[4][4];
            #pragma unroll
            for (int mt = 0; mt < 2; ++mt) {
                uint32_t ad = st + (uint32_t)((wm * 32 + mt * 16 + arow) * 80 +
                                              (ks * 16 + acolb) * 2);
                LDMX4(ah[mt], ad);
                LDMX4(al[mt], ad + MAT_B);
            }
            #pragma unroll
            for (int nt2 = 0; nt2 < 4; ++nt2) {
                uint32_t bd = st + 2 * MAT_B + (uint32_t)((wn * 64 + nt2 * 16 + brow) * 80 +
                                                          (ks * 16 + bcolb) * 2);
                LDMX4(bh[nt2], bd);
                LDMX4(bl[nt2], bd + MAT_B);
            }
            #pragma unroll
            for (int mt = 0; mt < 2; ++mt)
                #pragma unroll
                for (int nt = 0; nt < 8; ++nt) {
                    int n2 = nt >> 1, pr = (nt & 1) * 2;
                    MMA_BF16(c[mt][nt], ah[mt], bh[n2][pr], bh[n2][pr + 1]);
                    MMA_BF16(c[mt][nt], ah[mt], bl[n2][pr], bl[n2][pr + 1]);
                    MMA_BF16(c[mt][nt], al[mt], bh[n2][pr], bh[n2][pr + 1]);
                }
        }
    };

    ld_stage(0, 0);
    CP_COMMIT();
    const int KC = D_MODEL / BK;
    for (int kc = 0; kc < KC; ++kc) {
        int s = kc & 1;
        if (kc < KC - 1) {
            ld_stage(kc + 1, s ^ 1);
            CP_COMMIT();
            CP_WAIT(1);
        } else {
            CP_WAIT(0);
        }
        __syncthreads();
        compute(s);
        __syncthreads();
    }

    #pragma unroll
    for (int mt = 0; mt < 2; ++mt) {
        int r0 = bm + wm * 32 + mt * 16 + (lane >> 2);
        #pragma unroll
        for (int nt = 0; nt < 8; ++nt) {
            int col = bn + wn * 64 + nt * 8 + (lane & 3) * 2;
            float b0 = bias[col], b1 = bias[col + 1];
            if (r0 < Mvalid) {
                C[(size_t)r0 * D_MODEL + col]     = c[mt][nt][0] + b0;
                C[(size_t)r0 * D_MODEL + col + 1] = c[mt][nt][1] + b1;
            }
            if (r0 + 8 < Mvalid) {
                C[(size_t)(r0 + 8) * D_MODEL + col]     = c[mt][nt][2] + b0;
                C[(size_t)(r0 + 8) * D_MODEL + col + 1] = c[mt][nt][3] + b1;
            }
        }
    }
}

// ---------------- q GEMM: warp per output -------------------------------------
__global__ __launch_bounds__(256) void qgemm_kernel(const float* __restrict__ qx,
                                                    const float* __restrict__ qw,
                                                    const float* __restrict__ qb) {
    int gw = blockIdx.x * 8 + (threadIdx.x >> 5);
    int lane = threadIdx.x & 31;
    int row = gw / D_MODEL, col = gw - row * D_MODEL;
    const float4* x4 = (const float4*)(qx + (size_t)row * D_MODEL);
    const float4* w4 = (const float4*)(qw + (size_t)col * D_MODEL);
    float acc = 0.0f;
    #pragma unroll
    for (int i = 0; i < 6; ++i) {
        float4 a = x4[lane + 32 * i];
        float4 b = w4[lane + 32 * i];
        acc += a.x * b.x + a.y * b.y + a.z * b.z + a.w * b.w;
    }
    #pragma unroll
    for (int off = 16; off > 0; off >>= 1) acc += __shfl_xor_sync(0xffffffffu, acc, off);
    if (lane == 0) g_qpre[row * D_MODEL + col] = acc + qb[col];
}
__global__ void qln_kernel(const float* __restrict__ lw, const float* __restrict__ lb) {
    int row = blockIdx.x;
    int t = threadIdx.x;
    const float* x = g_qpre + row * D_MODEL;
    float v0 = x[t], v1 = x[t + 256], v2 = x[t + 512];
    __shared__ float red[256];
    red[t] = v0 + v1 + v2;
    __syncthreads();
    for (int s = 128; s > 0; s >>= 1) { if (t < s) red[t] += red[t + s]; __syncthreads(); }
    float mean = red[0] * (1.0f / D_MODEL);
    __syncthreads();
    float d0 = v0 - mean, d1 = v1 - mean, d2 = v2 - mean;
    red[t] = d0 * d0 + d1 * d1 + d2 * d2;
    __syncthreads();
    for (int s = 128; s > 0; s >>= 1) { if (t < s) red[t] += red[t + s]; __syncthreads(); }
    float rstd = rsqrtf(red[0] * (1.0f / D_MODEL) + LN_EPS);
    g_qln[row * D_MODEL + t]       = d0 * rstd * lw[t]       + lb[t];
    g_qln[row * D_MODEL + t + 256] = d1 * rstd * lw[t + 256] + lb[t + 256];
    g_qln[row * D_MODEL + t + 512] = d2 * rstd * lw[t + 512] + lb[t + 512];
}

// ---------------- kv LN stats: warp per row -----------------------------------
__global__ __launch_bounds__(256) void lnstats_kernel() {
    int row = blockIdx.x * 8 + (threadIdx.x >> 5);
    if (row >= M_ROWS) return;
    int lane = threadIdx.x & 31;
    const float4* x4 = (const float4*)(g_kv + (size_t)row * D_MODEL);
    float s1 = 0.0f, s2 = 0.0f;
    #pragma unroll
    for (int i = 0; i < 6; ++i) {
        float4 v = x4[lane + 32 * i];
        s1 += v.x + v.y + v.z + v.w;
        s2 += v.x * v.x + v.y * v.y + v.z * v.z + v.w * v.w;
    }
    #pragma unroll
    for (int off = 16; off > 0; off >>= 1) {
        s1 += __shfl_xor_sync(0xffffffffu, s1, off);
        s2 += __shfl_xor_sync(0xffffffffu, s2, off);
    }
    if (lane == 0) {
        float mean = s1 * (1.0f / D_MODEL);
        float var = s2 * (1.0f / D_MODEL) - mean * mean;
        g_mean[row] = mean;
        g_rstd[row] = rsqrtf(var + LN_EPS);
    }
}

// ---------------- attention: scores + softmax + A per (b,h,half) --------------
__global__ __launch_bounds__(256) void attn_kernel(const float* __restrict__ pos,
                                                   const float* __restrict__ lw,
                                                   const float* __restrict__ lb) {
    extern __shared__ float sm_tile[];
    int b = blockIdx.x, h = blockIdx.y, half = blockIdx.z;
    int tid = threadIdx.x;
    int w = tid >> 5, lane = tid & 31;

    __shared__ float4 qh4[NQ][D_HEAD / 4];
    __shared__ float e[NQ][200];

    const float4* lw4 = (const float4*)(lw + h * D_HEAD);
    const float4* lb4 = (const float4*)(lb + h * D_HEAD);
    for (int idx = tid; idx < P_TOK * (D_HEAD / 4); idx += 256) {
        int p = idx >> 4, d4 = idx & 15;
        int row = b * P_TOK + p;
        float m = g_mean[row], r = g_rstd[row];
        float4 raw = ((const float4*)(g_kv + (size_t)row * D_MODEL + h * D_HEAD))[d4];
        float4 pv = ((const float4*)(pos + (size_t)(half * P_TOK + p) * D_MODEL + h * D_HEAD))[d4];
        float4 wv = lw4[d4], bv = lb4[d4];
        float4 out;
        out.x = (raw.x - m) * r * wv.x + bv.x + pv.x;
        out.y = (raw.y - m) * r * wv.y + bv.y + pv.y;
        out.z = (raw.z - m) * r * wv.z + bv.z + pv.z;
        out.w = (raw.w - m) * r * wv.w + bv.w + pv.w;
        *(float4*)(sm_tile + p * TILE_LD + d4 * 4) = out;
    }
    for (int idx = tid; idx < NQ * (D_HEAD / 4); idx += 256) {
        int q = idx >> 4, d4 = idx & 15;
        qh4[q][d4] = ((const float4*)(g_qln + q * D_MODEL + h * D_HEAD))[d4];
    }
    __syncthreads();

    {
        int q = w;
        float mx = -1e30f;
        for (int p = lane; p < P_TOK; p += 32) {
            const float4* tp4 = (const float4*)(sm_tile + p * TILE_LD);
            float s = 0.0f;
            #pragma unroll
            for (int k = 0; k < D_HEAD / 4; ++k) {
                float4 t = tp4[k];
                float4 qv = qh4[q][k];
                s += t.x * qv.x + t.y * qv.y + t.z * qv.z + t.w * qv.w;
            }
            s *= 0.125f;
            e[q][p] = s;
            mx = fmaxf(mx, s);
        }
        #pragma unroll
        for (int off = 16; off > 0; off >>= 1) mx = fmaxf(mx, __shfl_xor_sync(0xffffffffu, mx, off));
        float sum = 0.0f;
        for (int p = lane; p < P_TOK; p += 32) {
            float t = __expf(e[q][p] - mx);
            e[q][p] = t;
            sum += t;
        }
        #pragma unroll
        for (int off = 16; off > 0; off >>= 1) sum += __shfl_xor_sync(0xffffffffu, sum, off);
        if (lane == 0) {
            int idx = ((half * BATCH + b) * NUM_HEADS + h) * NQ + q;
            g_m[idx] = mx;
            g_z[idx] = sum;
        }
    }
    __syncthreads();

    for (int ii = tid; ii < NQ * D_HEAD; ii += 256) {
        int q = ii >> 6, d = ii & 63;
        float acc = 0.0f;
        const float* tcol = sm_tile + d;
        #pragma unroll 4
        for (int p = 0; p < 196; p += 4) {
            float4 ev = *(const float4*)&e[q][p];
            acc += ev.x * tcol[p * TILE_LD] + ev.y * tcol[(p + 1) * TILE_LD] +
                   ev.z * tcol[(p + 2) * TILE_LD] + ev.w * tcol[(p + 3) * TILE_LD];
        }
        acc += e[q][196] * tcol[196 * TILE_LD];
        g_a[((((size_t)half * BATCH + b) * NUM_HEADS + h) * NQ + q) * D_HEAD + d] = acc;
    }
}

// ---------------- merge: one block per pair, loop q ---------------------------
__global__ __launch_bounds__(192) void merge_kernel() {
    int pair = blockIdx.x;
    int i = pair >> 4, j = pair & 15;
    int tid = threadIdx.x;
    __shared__ float c1s[NQ][NUM_HEADS], c2s[NQ][NUM_HEADS];
    if (tid < NQ * NUM_HEADS) {
        int q = tid / NUM_HEADS, h = tid - q * NUM_HEADS;
        int i1 = (i * NUM_HEADS + h) * NQ + q;
        int i2 = ((BATCH + j) * NUM_HEADS + h) * NQ + q;
        float m1 = g_m[i1], m2 = g_m[i2];
        float z1 = g_z[i1], z2 = g_z[i2];
        float m = fmaxf(m1, m2);
        float e1 = __expf(m1 - m), e2 = __expf(m2 - m);
        float zinv = 1.0f / (e1 * z1 + e2 * z2);
        c1s[q][h] = e1 * zinv;
        c2s[q][h] = e2 * zinv;
    }
    __syncthreads();
    int o0 = tid * 4;
    int h = o0 >> 6, d = o0 & 63;
    #pragma unroll
    for (int q = 0; q < NQ; ++q) {
        float4 a1 = *(const float4*)(g_a + ((((size_t)0 * BATCH + i) * NUM_HEADS + h) * NQ + q) * D_HEAD + d);
        float4 a2 = *(const float4*)(g_a + ((((size_t)1 * BATCH + j) * NUM_HEADS + h) * NQ + q) * D_HEAD + d);
        float w1 = c1s[q][h], w2 = c2s[q][h];
        float4 v;
        v.x = w1 * a1.x - w2 * a2.x;
        v.y = w1 * a1.y - w2 * a2.y;
        v.z = w1 * a1.z - w2 * a2.z;
        v.w = w1 * a1.w - w2 * a2.w;
        ushort4 hi, lo;
        split4(v, hi, lo);
        size_t row = (size_t)pair * NQ + q;
        ((ushort4*)(g_ach + row * D_MODEL))[tid] = hi;
        ((ushort4*)(g_acl + row * D_MODEL))[tid] = lo;
    }
}

// ---------------- launch ------------------------------------------------------
extern "C" void kernel_launch(void* const* d_in, const int* in_sizes, int n_in,
                              void* d_out, int out_size) {
    const float* q_x   = (const float*)d_in[0];
    const float* kv_x  = (const float*)d_in[1];
    const float* pos   = (const float*)d_in[2];
    const float* q_w   = (const float*)d_in[3];
    const float* q_b   = (const float*)d_in[4];
    const float* kv_w  = (const float*)d_in[5];
    const float* kv_b  = (const float*)d_in[6];
    const float* out_w = (const float*)d_in[7];
    const float* out_b = (const float*)d_in[8];
    const float* lnq_w = (const float*)d_in[9];
    const float* lnq_b = (const float*)d_in[10];
    const float* lnkv_w = (const float*)d_in[11];
    const float* lnkv_b = (const float*)d_in[12];
    float* out = (float*)d_out;

    __nv_bfloat16 *p_xh, *p_xl, *p_wh, *p_wl, *p_owh, *p_owl, *p_ach, *p_acl;
    float* p_kv;
    cudaGetSymbolAddress((void**)&p_xh, g_xh);
    cudaGetSymbolAddress((void**)&p_xl, g_xl);
    cudaGetSymbolAddress((void**)&p_wh, g_wh);
    cudaGetSymbolAddress((void**)&p_wl, g_wl);
    cudaGetSymbolAddress((void**)&p_owh, g_owh);
    cudaGetSymbolAddress((void**)&p_owl, g_owl);
    cudaGetSymbolAddress((void**)&p_ach, g_ach);
    cudaGetSymbolAddress((void**)&p_acl, g_acl);
    cudaGetSymbolAddress((void**)&p_kv, g_kv);

    // one-time setup (created on the correctness call, before graph capture)
    static cudaStream_t s1 = nullptr, s2 = nullptr;
    static cudaEvent_t evFork = nullptr, evQ = nullptr, evW = nullptr;
    if (!s1) {
        cudaStreamCreateWithFlags(&s1, cudaStreamNonBlocking);
        cudaStreamCreateWithFlags(&s2, cudaStreamNonBlocking);
        cudaEventCreateWithFlags(&evFork, cudaEventDisableTiming);
        cudaEventCreateWithFlags(&evQ, cudaEventDisableTiming);
        cudaEventCreateWithFlags(&evW, cudaEventDisableTiming);
        int gemm_smem = 2 * STAGE_B;
        cudaFuncSetAttribute(gemm_bf16, cudaFuncAttributeMaxDynamicSharedMemorySize, gemm_smem);
        int tile_bytes = P_TOK * TILE_LD * sizeof(float);
        cudaFuncSetAttribute(attn_kernel, cudaFuncAttributeMaxDynamicSharedMemorySize, tile_bytes);
    }
    int gemm_smem = 2 * STAGE_B;                       // 81920
    int tile_bytes = P_TOK * TILE_LD * sizeof(float);  // 53584

    // fork side streams off the (captured) default stream
    cudaEventRecord(evFork, 0);
    cudaStreamWaitEvent(s1, evFork, 0);
    cudaStreamWaitEvent(s2, evFork, 0);

    // s1: q path
    qgemm_kernel<<<(NQ * D_MODEL) / 8, 256, 0, s1>>>(q_x, q_w, q_b);
    qln_kernel<<<NQ, 256, 0, s1>>>(lnq_w, lnq_b);
    cudaEventRecord(evQ, s1);

    // s2: out_w split (only needed by the last GEMM)
    splitw_kernel<<<NW4 / 256, 256, 0, s2>>>(out_w, p_owh, p_owl);
    cudaEventRecord(evW, s2);

    // main chain on default stream
    split_kv_kernel<<<(NX4 + NW4 + 255) / 256, 256>>>(kv_x, kv_w);
    gemm_bf16<<<dim3(6, 25), 256, gemm_smem>>>(p_xh, p_xl, p_wh, p_wl, kv_b, p_kv, M_ROWS);
    lnstats_kernel<<<(M_ROWS + 7) / 8, 256>>>();
    cudaStreamWaitEvent(0, evQ, 0);
    attn_kernel<<<dim3(BATCH, NUM_HEADS, 2), 256, tile_bytes>>>(pos, lnkv_w, lnkv_b);
    merge_kernel<<<PAIRS, 192>>>();
    cudaStreamWaitEvent(0, evW, 0);
    gemm_bf16<<<dim3(6, 16), 256, gemm_smem>>>(p_ach, p_acl, p_owh, p_owl, out_b, out, OUT_ROWS);
}